// round 5
// baseline (speedup 1.0000x reference)
#include <cuda_runtime.h>
#include <cuda_fp16.h>
#include <cuda_fp8.h>
#include <math.h>
#include <stdint.h>

#define T_ 4096
#define D_ 512
#define TR_ 64
#define CC_ 64
#define L_ 3
#define F_ 8192
#define NCH_ 4096
#define NCHUNK_ 16
#define CHUNK_ 256

#define LO_SCALE 16384.f
#define LO_INV   (1.f/16384.f)

// ---------------- scratch ----------------
__device__ float g_x[T_*D_];
__device__ float g_trct[T_*128];
__device__ float g_u[T_*TR_];
__device__ float g_v[T_*CC_];
__device__ float2 g_Bend[NCHUNK_*NCH_];
__device__ float2 g_Amat[NCHUNK_*NCH_];
__device__ float2 g_sinit[NCHUNK_*NCH_];
__device__ float g_h[T_*D_];
__device__ float g_ztmp[T_*D_];
// features: fp16 hi + e4m3 full + e4m3 scaled-residual
__device__ __half  g_sclh[(size_t)T_*F_];
__device__ uint8_t g_scl8[(size_t)T_*F_];
__device__ uint8_t g_scll8[(size_t)T_*F_];
// weights (3 forms each)
__device__ __half  g_w0h[L_*D_*F_];
__device__ uint8_t g_w08[L_*D_*F_];
__device__ uint8_t g_w0l8[L_*D_*F_];
__device__ __half  g_w1h[L_*D_*D_];
__device__ uint8_t g_w18[L_*D_*D_];
__device__ uint8_t g_w1l8[L_*D_*D_];
__device__ __half  g_wph[L_*128*D_];
__device__ uint8_t g_wp8[L_*128*D_];
__device__ uint8_t g_wpl8[L_*128*D_];
// activations (3 forms)
__device__ __half  g_z0h[T_*D_];
__device__ uint8_t g_z08[T_*D_];
__device__ uint8_t g_z0l8[T_*D_];
__device__ __half  g_xh[T_*D_];
__device__ uint8_t g_x8[T_*D_];
__device__ uint8_t g_xl8[T_*D_];

// ---------------- low-level helpers ----------------
__device__ __forceinline__ uint32_t sptr(const void* p){
  return (uint32_t)__cvta_generic_to_shared(p);
}
__device__ __forceinline__ void cp16(uint32_t s, const void* g){
  asm volatile("cp.async.cg.shared.global [%0], [%1], 16;" :: "r"(s), "l"(g));
}
#define CP_COMMIT() asm volatile("cp.async.commit_group;" ::: "memory")
#define CP_WAIT(n)  asm volatile("cp.async.wait_group %0;" :: "n"(n) : "memory")

__device__ __forceinline__ void ldsm4(uint32_t* r, uint32_t a){
  asm volatile("ldmatrix.sync.aligned.m8n8.x4.shared.b16 {%0,%1,%2,%3}, [%4];"
    : "=r"(r[0]),"=r"(r[1]),"=r"(r[2]),"=r"(r[3]) : "r"(a));
}
__device__ __forceinline__ void mma_h(float* d, const uint32_t* a, const uint32_t* b){
  asm volatile("mma.sync.aligned.m16n8k16.row.col.f32.f16.f16.f32 "
    "{%0,%1,%2,%3}, {%4,%5,%6,%7}, {%8,%9}, {%0,%1,%2,%3};"
    : "+f"(d[0]),"+f"(d[1]),"+f"(d[2]),"+f"(d[3])
    : "r"(a[0]),"r"(a[1]),"r"(a[2]),"r"(a[3]), "r"(b[0]),"r"(b[1]));
}
__device__ __forceinline__ void mma_q(float* d, const uint32_t* a, const uint32_t* b){
  asm volatile("mma.sync.aligned.m16n8k32.row.col.f32.e4m3.e4m3.f32 "
    "{%0,%1,%2,%3}, {%4,%5,%6,%7}, {%8,%9}, {%0,%1,%2,%3};"
    : "+f"(d[0]),"+f"(d[1]),"+f"(d[2]),"+f"(d[3])
    : "r"(a[0]),"r"(a[1]),"r"(a[2]),"r"(a[3]), "r"(b[0]),"r"(b[1]));
}
__device__ __forceinline__ uint8_t f2e4m3(float v){
  __nv_fp8_storage_t s = __nv_cvt_float_to_fp8(v, __NV_SATFINITE, __NV_E4M3);
  return (uint8_t)s;
}
__device__ __forceinline__ void emit3(float v, __half* h, uint8_t* q8, uint8_t* ql8){
  __half hh = __float2half_rn(v);
  *h = hh;
  *q8 = f2e4m3(v);
  *ql8 = f2e4m3((v - __half2float(hh)) * LO_SCALE);
}

// ---------------- prep kernels ----------------
__global__ void split3(const float* __restrict__ src, __half* __restrict__ hi,
                       uint8_t* __restrict__ q8, uint8_t* __restrict__ ql8, int n){
  int i = blockIdx.x*blockDim.x + threadIdx.x;
  if (i < n) emit3(src[i], hi+i, q8+i, ql8+i);
}

__global__ void copy_split_x(const float* __restrict__ src){
  int i = blockIdx.x*blockDim.x + threadIdx.x;
  float v = src[i];
  g_x[i] = v;
  emit3(v, g_xh+i, g_x8+i, g_xl8+i);
}

__global__ void prep_wproj(const float* __restrict__ Wtr, const float* __restrict__ Wc){
  int idx = blockIdx.x*blockDim.x + threadIdx.x;
  if (idx >= L_*128*D_) return;
  int l = idx / (128*D_);
  int rem = idx % (128*D_);
  int row = rem / D_, k = rem % D_;
  float v = (row < 64) ? Wtr[((size_t)l*64+row)*D_+k] : Wc[((size_t)l*64+row-64)*D_+k];
  emit3(v, g_wph+idx, g_wp8+idx, g_wpl8+idx);
}

// ================= fp16 hi GEMM: C[m,n] = sum_k Ah[m,k]*Bh[n,k] =================
// BM=BN=128, BK=64, 256 threads (8 warps 4x2), warp tile 32x64.
#define PADH 72                        // halves per SMEM row (64 data + 8 pad)
#define TILEH (128*PADH)               // halves per tile
#define HI_SMEM (2*2*TILEH*2)          // 2 stages * 2 tensors * bytes = 73728

__device__ __forceinline__ void stage_load_hi(
    __half* s, const __half* Ah, const __half* Bh,
    int bm, int bn, int K, int k0, int tid)
{
  const __half* src[2] = {Ah, Bh};
  #pragma unroll
  for (int t=0;t<2;t++){
    int rb = (t==0)? bm : bn;
    #pragma unroll
    for (int q=0;q<4;q++){
      int chunk = tid + q*256;             // 1024 chunks per tensor
      int row = chunk>>3, cc = chunk&7;
      uint32_t so = sptr(s + t*TILEH + row*PADH + cc*8);
      cp16(so, src[t] + (size_t)(rb+row)*K + k0 + cc*8);
    }
  }
}

__global__ void __launch_bounds__(256)
gemm_hi(const __half* __restrict__ Ah, const __half* __restrict__ Bh,
        float* __restrict__ C, int K, int Nc)
{
  extern __shared__ __half smh[];
  const int tid = threadIdx.x;
  const int wid = tid>>5, lane = tid&31;
  const int bm = blockIdx.y*128, bn = blockIdx.x*128;
  const int wm = (wid>>1)*32;
  const int wn = (wid&1)*64;
  const int KT = K>>6;

  float acc[2][8][4];
  #pragma unroll
  for (int i=0;i<2;i++)
    #pragma unroll
    for (int j=0;j<8;j++)
      #pragma unroll
      for (int q=0;q<4;q++) acc[i][j][q]=0.f;

  stage_load_hi(smh, Ah, Bh, bm, bn, K, 0, tid);
  CP_COMMIT();

  const int arow = lane & 15;
  const int acol8 = (lane>>4)*8;
  const int brow = (lane&7) + ((lane>>4)<<3);
  const int bsel = ((lane>>3)&1)*8;

  for (int c=0; c<KT; c++){
    if (c+1 < KT){
      stage_load_hi(smh + ((c+1)&1)*2*TILEH, Ah, Bh, bm, bn, K, (c+1)*64, tid);
      CP_COMMIT();
      CP_WAIT(1);
    } else {
      CP_WAIT(0);
    }
    __syncthreads();

    __half* s = smh + (c&1)*2*TILEH;
    const uint32_t sA = sptr(s);
    const uint32_t sB = sA + TILEH*2;

    #pragma unroll
    for (int ks=0; ks<4; ks++){
      uint32_t ah[2][4], bh[4][4];
      #pragma unroll
      for (int mi=0; mi<2; mi++){
        uint32_t off = (uint32_t)((wm + mi*16 + arow)*PADH + ks*16 + acol8)*2;
        ldsm4(ah[mi], sA + off);
      }
      #pragma unroll
      for (int p=0; p<4; p++){
        uint32_t off = (uint32_t)((wn + p*16 + brow)*PADH + ks*16 + bsel)*2;
        ldsm4(bh[p], sB + off);
      }
      #pragma unroll
      for (int mi=0; mi<2; mi++)
        #pragma unroll
        for (int p=0; p<4; p++)
          #pragma unroll
          for (int h=0; h<2; h++)
            mma_h(acc[mi][p*2+h], ah[mi], &bh[p][h*2]);
    }
    __syncthreads();
  }

  #pragma unroll
  for (int mi=0; mi<2; mi++){
    const int r0 = bm + wm + mi*16 + (lane>>2);
    const int c0 = bn + wn + (lane&3)*2;
    #pragma unroll
    for (int ni=0; ni<8; ni++){
      *(float2*)(C + (size_t)r0*Nc + c0 + ni*8)     = make_float2(acc[mi][ni][0], acc[mi][ni][1]);
      *(float2*)(C + (size_t)(r0+8)*Nc + c0 + ni*8) = make_float2(acc[mi][ni][2], acc[mi][ni][3]);
    }
  }
}

// ================= fp8 cross GEMM: C += (Ah8*Bl8 + Al8*Bh8) * LO_INV =================
// BM=BN=128, BK=64 (bytes), rows padded to 80 B. 256 threads, warp tile 32x64.
#define PAD8 80
#define TILE8 (128*PAD8)               // bytes per tile
#define CR_SMEM (2*4*TILE8)            // 2 stages * 4 tensors = 81920

__device__ __forceinline__ void stage_load_q(
    uint8_t* s, const uint8_t* Ah8, const uint8_t* Al8,
    const uint8_t* Bh8, const uint8_t* Bl8,
    int bm, int bn, int K, int k0, int tid)
{
  const uint8_t* src[4] = {Ah8, Al8, Bh8, Bl8};
  #pragma unroll
  for (int t=0;t<4;t++){
    int rb = (t<2)? bm : bn;
    #pragma unroll
    for (int q=0;q<2;q++){
      int chunk = tid + q*256;             // 512 chunks per tensor
      int row = chunk>>2, cc = chunk&3;
      uint32_t so = sptr(s + t*TILE8 + row*PAD8 + cc*16);
      cp16(so, src[t] + (size_t)(rb+row)*K + k0 + cc*16);
    }
  }
}

__global__ void __launch_bounds__(256)
gemm_cross(const uint8_t* __restrict__ Ah8, const uint8_t* __restrict__ Al8,
           const uint8_t* __restrict__ Bh8, const uint8_t* __restrict__ Bl8,
           float* __restrict__ C, int K, int Nc)
{
  extern __shared__ uint8_t sm8[];
  const int tid = threadIdx.x;
  const int wid = tid>>5, lane = tid&31;
  const int bm = blockIdx.y*128, bn = blockIdx.x*128;
  const int wm = (wid>>1)*32;
  const int wn = (wid&1)*64;
  const int KT = K>>6;

  float acc[2][8][4];
  #pragma unroll
  for (int i=0;i<2;i++)
    #pragma unroll
    for (int j=0;j<8;j++)
      #pragma unroll
      for (int q=0;q<4;q++) acc[i][j][q]=0.f;

  stage_load_q(sm8, Ah8, Al8, Bh8, Bl8, bm, bn, K, 0, tid);
  CP_COMMIT();

  const int arow = lane & 15;
  const int acolB = (lane>>4)*16;            // byte offset for k16 half
  const int brow = (lane&7) + ((lane>>4)<<3);
  const int bselB = ((lane>>3)&1)*16;

  for (int c=0; c<KT; c++){
    if (c+1 < KT){
      stage_load_q(sm8 + ((c+1)&1)*4*TILE8, Ah8, Al8, Bh8, Bl8, bm, bn, K, (c+1)*64, tid);
      CP_COMMIT();
      CP_WAIT(1);
    } else {
      CP_WAIT(0);
    }
    __syncthreads();

    uint8_t* s = sm8 + (c&1)*4*TILE8;
    const uint32_t sAh = sptr(s);
    const uint32_t sAl = sAh + TILE8;
    const uint32_t sBh = sAh + 2*TILE8;
    const uint32_t sBl = sAh + 3*TILE8;

    #pragma unroll
    for (int ks=0; ks<2; ks++){
      uint32_t ah[2][4], al[2][4], bh[4][4], bl[4][4];
      #pragma unroll
      for (int mi=0; mi<2; mi++){
        uint32_t off = (uint32_t)((wm + mi*16 + arow)*PAD8 + ks*32 + acolB);
        ldsm4(ah[mi], sAh + off);
        ldsm4(al[mi], sAl + off);
      }
      #pragma unroll
      for (int p=0; p<4; p++){
        uint32_t off = (uint32_t)((wn + p*16 + brow)*PAD8 + ks*32 + bselB);
        ldsm4(bh[p], sBh + off);
        ldsm4(bl[p], sBl + off);
      }
      #pragma unroll
      for (int mi=0; mi<2; mi++)
        #pragma unroll
        for (int p=0; p<4; p++)
          #pragma unroll
          for (int h=0; h<2; h++){
            const int ni = p*2 + h;
            mma_q(acc[mi][ni], ah[mi], &bl[p][h*2]);
            mma_q(acc[mi][ni], al[mi], &bh[p][h*2]);
          }
    }
    __syncthreads();
  }

  #pragma unroll
  for (int mi=0; mi<2; mi++){
    const int r0 = bm + wm + mi*16 + (lane>>2);
    const int c0 = bn + wn + (lane&3)*2;
    #pragma unroll
    for (int ni=0; ni<8; ni++){
      float2* p0 = (float2*)(C + (size_t)r0*Nc + c0 + ni*8);
      float2* p1 = (float2*)(C + (size_t)(r0+8)*Nc + c0 + ni*8);
      float2 v0 = *p0, v1 = *p1;
      v0.x += acc[mi][ni][0]*LO_INV; v0.y += acc[mi][ni][1]*LO_INV;
      v1.x += acc[mi][ni][2]*LO_INV; v1.y += acc[mi][ni][3]*LO_INV;
      *p0 = v0; *p1 = v1;
    }
  }
}

// ---------------- u, v with normalization ----------------
__global__ void uv_kernel(){
  int t = blockIdx.x;
  int i = threadIdx.x;
  float uu = fabsf(g_trct[t*128 + i]);
  float vv = fabsf(g_trct[t*128 + 64 + i]);
  __shared__ float su[64], sv[64];
  su[i]=uu; sv[i]=vv; __syncthreads();
  for (int s=32; s>0; s>>=1){
    if (i<s){ su[i]+=su[i+s]; sv[i]+=sv[i+s]; }
    __syncthreads();
  }
  float scale = __fdividef(1.0f, 1e-8f + su[0]*sv[0]);
  g_u[t*TR_+i] = uu;
  g_v[t*CC_+i] = vv*scale;
}

__device__ __forceinline__ void make_decay(float ai, float bj, float& dre, float& dim){
  double rho = exp(-(double)fabsf(ai));
  double sb, cb; sincos((double)bj, &sb, &cb);
  dre = (float)(rho*cb); dim = (float)(rho*sb);
}

__global__ void scan_passA(const unsigned* __restrict__ start,
                           const float* __restrict__ a, const float* __restrict__ b,
                           int layer){
  const int i = blockIdx.y;
  const int c = blockIdx.x;
  const int j = threadIdx.x;
  const float ai = a[layer*TR_ + i];
  const float bj = b[layer*CC_ + j];
  float dre, dim;
  make_decay(ai, bj, dre, dim);
  float sre=0.f, sim=0.f;
  int reset = 0;
  const int t0 = c*CHUNK_;
  for (int t=t0; t<t0+CHUNK_; t++){
    if (start[t]){ sre=0.f; sim=0.f; reset=1; }
    float p = g_u[t*TR_+i]*g_v[t*CC_+j];
    float nre = fmaf(sre,dre, fmaf(-sim,dim,p));
    float nim = fmaf(sre,dim, sim*dre);
    sre=nre; sim=nim;
  }
  const int ch = i*CC_+j;
  g_Bend[c*NCH_+ch]=make_float2(sre,sim);
  float2 A;
  if (reset){ A=make_float2(0.f,0.f); }
  else {
    double rhoL = exp(-(double)fabsf(ai)*(double)CHUNK_);
    double sL,cL; sincos((double)bj*(double)CHUNK_, &sL,&cL);
    A = make_float2((float)(rhoL*cL), (float)(rhoL*sL));
  }
  g_Amat[c*NCH_+ch]=A;
}

__global__ void scan_passB(const float* __restrict__ state, int layer){
  int ch = blockIdx.x*blockDim.x + threadIdx.x;
  float sre = state[layer*NCH_ + ch];
  float sim = 0.f;
  #pragma unroll
  for (int c=0;c<NCHUNK_;c++){
    g_sinit[c*NCH_+ch] = make_float2(sre,sim);
    float2 A = g_Amat[c*NCH_+ch];
    float2 B = g_Bend[c*NCH_+ch];
    float nre = A.x*sre - A.y*sim + B.x;
    float nim = A.x*sim + A.y*sre + B.y;
    sre=nre; sim=nim;
  }
}

// full scan + feature emission in 3 forms
__global__ void scan_passC(const unsigned* __restrict__ start,
                           const float* __restrict__ a, const float* __restrict__ b,
                           int layer){
  const int i = blockIdx.y, c = blockIdx.x, j = threadIdx.x;
  float dre, dim;
  make_decay(a[layer*TR_+i], b[layer*CC_+j], dre, dim);
  const int ch = i*CC_+j;
  float2 s0 = g_sinit[c*NCH_+ch];
  float sre=s0.x, sim=s0.y;
  const int t0=c*CHUNK_;
  for (int t=t0;t<t0+CHUNK_;t++){
    if (start[t]){ sre=0.f; sim=0.f; }
    float p = g_u[t*TR_+i]*g_v[t*CC_+j];
    float nre = fmaf(sre,dre, fmaf(-sim,dim,p));
    float nim = fmaf(sre,dim, sim*dre);
    sre=nre; sim=nim;
    float r2 = fmaf(sre,sre, sim*sim);
    float f;
    if (r2 > 1e-24f){
      float rr = sqrtf(r2);
      f = __fdividef(log1pf(rr), rr);
    } else {
      f = 1.f;
    }
    float fs = f*sim, fc = f*sre;
    size_t o0 = (size_t)t*F_ + ch;
    size_t o1 = o0 + NCH_;
    emit3(fs, g_sclh+o0, g_scl8+o0, g_scll8+o0);
    emit3(fc, g_sclh+o1, g_scl8+o1, g_scll8+o1);
  }
}

// ================= LayerNorm + leaky ReLU =================
__device__ __forceinline__ void reduce2(float &s, float &ss){
  __shared__ float sh[8], sh2[8];
  int lane = threadIdx.x & 31, w = threadIdx.x >> 5;
  #pragma unroll
  for (int o=16;o>0;o>>=1){
    s  += __shfl_down_sync(0xffffffffu, s,  o);
    ss += __shfl_down_sync(0xffffffffu, ss, o);
  }
  if (lane==0){ sh[w]=s; sh2[w]=ss; }
  __syncthreads();
  if (w==0){
    s  = (lane<8)? sh[lane]  : 0.f;
    ss = (lane<8)? sh2[lane] : 0.f;
    #pragma unroll
    for (int o=4;o>0;o>>=1){
      s  += __shfl_down_sync(0xffffffffu, s,  o);
      ss += __shfl_down_sync(0xffffffffu, ss, o);
    }
    if (lane==0){ sh[0]=s; sh2[0]=ss; }
  }
  __syncthreads();
  s = sh[0]; ss = sh2[0];
}

__global__ void ln_leaky(const float* __restrict__ zin, const float* __restrict__ bias,
                         const float* __restrict__ gamma, const float* __restrict__ beta,
                         float* __restrict__ zout, float* __restrict__ xacc,
                         __half* __restrict__ zh, uint8_t* __restrict__ z8, uint8_t* __restrict__ zl8,
                         __half* __restrict__ xh, uint8_t* __restrict__ x8, uint8_t* __restrict__ xl8){
  const int t = blockIdx.x;
  const int tid = threadIdx.x;
  float v0 = zin[t*D_ + tid]       + bias[tid];
  float v1 = zin[t*D_ + 256 + tid] + bias[256+tid];
  float s = v0+v1;
  float ss = v0*v0 + v1*v1;
  reduce2(s, ss);
  float m = s * (1.f/512.f);
  float var = ss * (1.f/512.f) - m*m;
  float rinv = rsqrtf(var + 1e-5f);
  float y0 = (v0 - m)*rinv*gamma[tid]     + beta[tid];
  float y1 = (v1 - m)*rinv*gamma[256+tid] + beta[256+tid];
  y0 = (y0 > 0.f) ? y0 : 0.01f*y0;
  y1 = (y1 > 0.f) ? y1 : 0.01f*y1;
  if (zout){
    zout[t*D_ + tid]       = y0;
    zout[t*D_ + 256 + tid] = y1;
  }
  if (xacc){
    float x0 = xacc[t*D_ + tid]       + y0;
    float x1 = xacc[t*D_ + 256 + tid] + y1;
    xacc[t*D_ + tid]       = x0;
    xacc[t*D_ + 256 + tid] = x1;
    if (xh){
      emit3(x0, xh + t*D_ + tid,       x8 + t*D_ + tid,       xl8 + t*D_ + tid);
      emit3(x1, xh + t*D_ + 256 + tid, x8 + t*D_ + 256 + tid, xl8 + t*D_ + 256 + tid);
    }
  }
  if (zh){
    emit3(y0, zh + t*D_ + tid,       z8 + t*D_ + tid,       zl8 + t*D_ + tid);
    emit3(y1, zh + t*D_ + 256 + tid, z8 + t*D_ + 256 + tid, zl8 + t*D_ + 256 + tid);
  }
}

// ================= launcher =================
extern "C" void kernel_launch(void* const* d_in, const int* in_sizes, int n_in,
                              void* d_out, int out_size) {
  const float*    x     = (const float*)d_in[0];
  const float*    state = (const float*)d_in[1];
  const unsigned* start = (const unsigned*)d_in[2];
  const float*    Wtr   = (const float*)d_in[3];
  const float*    Wc    = (const float*)d_in[4];
  const float*    a     = (const float*)d_in[5];
  const float*    b     = (const float*)d_in[6];
  const float*    W0    = (const float*)d_in[7];
  const float*    b0    = (const float*)d_in[8];
  const float*    g0    = (const float*)d_in[9];
  const float*    beta0 = (const float*)d_in[10];
  const float*    W1    = (const float*)d_in[11];
  const float*    b1    = (const float*)d_in[12];
  const float*    g1    = (const float*)d_in[13];
  const float*    beta1 = (const float*)d_in[14];
  float* out = (float*)d_out;

  float *px, *ptrct, *ph, *pzt;
  __half *psh, *pw0h, *pw1h, *pwph, *pz0h, *pxh;
  uint8_t *ps8, *psl8, *pw08, *pw0l8, *pw18, *pw1l8, *pwp8, *pwpl8;
  uint8_t *pz08, *pz0l8, *px8, *pxl8;
  cudaGetSymbolAddress((void**)&px,    g_x);
  cudaGetSymbolAddress((void**)&ptrct, g_trct);
  cudaGetSymbolAddress((void**)&ph,    g_h);
  cudaGetSymbolAddress((void**)&pzt,   g_ztmp);
  cudaGetSymbolAddress((void**)&psh,   g_sclh);
  cudaGetSymbolAddress((void**)&ps8,   g_scl8);
  cudaGetSymbolAddress((void**)&psl8,  g_scll8);
  cudaGetSymbolAddress((void**)&pw0h,  g_w0h);
  cudaGetSymbolAddress((void**)&pw08,  g_w08);
  cudaGetSymbolAddress((void**)&pw0l8, g_w0l8);
  cudaGetSymbolAddress((void**)&pw1h,  g_w1h);
  cudaGetSymbolAddress((void**)&pw18,  g_w18);
  cudaGetSymbolAddress((void**)&pw1l8, g_w1l8);
  cudaGetSymbolAddress((void**)&pwph,  g_wph);
  cudaGetSymbolAddress((void**)&pwp8,  g_wp8);
  cudaGetSymbolAddress((void**)&pwpl8, g_wpl8);
  cudaGetSymbolAddress((void**)&pz0h,  g_z0h);
  cudaGetSymbolAddress((void**)&pz08,  g_z08);
  cudaGetSymbolAddress((void**)&pz0l8, g_z0l8);
  cudaGetSymbolAddress((void**)&pxh,   g_xh);
  cudaGetSymbolAddress((void**)&px8,   g_x8);
  cudaGetSymbolAddress((void**)&pxl8,  g_xl8);

  cudaFuncSetAttribute(gemm_hi,    cudaFuncAttributeMaxDynamicSharedMemorySize, HI_SMEM);
  cudaFuncSetAttribute(gemm_cross, cudaFuncAttributeMaxDynamicSharedMemorySize, CR_SMEM);

  copy_split_x<<<(T_*D_)/256, 256>>>(x);
  split3<<<(L_*D_*F_ + 255)/256, 256>>>(W0, pw0h, pw08, pw0l8, L_*D_*F_);
  split3<<<(L_*D_*D_ + 255)/256, 256>>>(W1, pw1h, pw18, pw1l8, L_*D_*D_);
  prep_wproj<<<(L_*128*D_ + 255)/256, 256>>>(Wtr, Wc);

  for (int l=0; l<L_; l++){
    // [tr|ct] = x @ [Wtr;Wc]^T  (M=4096, N=128, K=512)
    {
      size_t off = (size_t)l*128*D_;
      gemm_hi<<<dim3(1, T_/128), 256, HI_SMEM>>>(pxh, pwph + off, ptrct, D_, 128);
      gemm_cross<<<dim3(1, T_/128), 256, CR_SMEM>>>(px8, pxl8, pwp8 + off, pwpl8 + off, ptrct, D_, 128);
    }
    uv_kernel<<<T_, 64>>>();

    scan_passA<<<dim3(NCHUNK_, TR_), CC_>>>(start, a, b, l);
    scan_passB<<<NCH_/256, 256>>>(state, l);
    scan_passC<<<dim3(NCHUNK_, TR_), CC_>>>(start, a, b, l);

    // h = scaled @ W0^T   (M=4096, N=512, K=8192)
    {
      size_t off = (size_t)l*D_*F_;
      gemm_hi<<<dim3(D_/128, T_/128), 256, HI_SMEM>>>(psh, pw0h + off, ph, F_, D_);
      gemm_cross<<<dim3(D_/128, T_/128), 256, CR_SMEM>>>(ps8, psl8, pw08 + off, pw0l8 + off, ph, F_, D_);
    }
    ln_leaky<<<T_, 256>>>(ph, b0 + l*D_, g0 + l*D_, beta0 + l*D_,
                          nullptr, nullptr, pz0h, pz08, pz0l8, nullptr, nullptr, nullptr);

    // h = z0 @ W1^T   (M=4096, N=512, K=512)
    {
      size_t off = (size_t)l*D_*D_;
      gemm_hi<<<dim3(D_/128, T_/128), 256, HI_SMEM>>>(pz0h, pw1h + off, ph, D_, D_);
      gemm_cross<<<dim3(D_/128, T_/128), 256, CR_SMEM>>>(pz08, pz0l8, pw18 + off, pw1l8 + off, ph, D_, D_);
    }
    float* zo = (l == L_-1) ? out : pzt;
    bool last = (l == L_-1);
    ln_leaky<<<T_, 256>>>(ph, b1 + l*D_, g1 + l*D_, beta1 + l*D_,
                          zo, px, nullptr, nullptr, nullptr,
                          last ? nullptr : pxh, last ? nullptr : px8, last ? nullptr : pxl8);
  }
}

// round 6
// speedup vs baseline: 1.4597x; 1.4597x over previous
#include <cuda_runtime.h>
#include <cuda_fp16.h>
#include <math.h>
#include <stdint.h>

#define T_ 4096
#define D_ 512
#define TR_ 64
#define CC_ 64
#define L_ 3
#define F_ 8192
#define NCH_ 4096
#define NCHUNK_ 16
#define CHUNK_ 256

// ---------------- scratch ----------------
__device__ float g_x[T_*D_];
__device__ float g_trct[T_*128];
__device__ float g_u[T_*TR_];
__device__ float g_v[T_*CC_];
__device__ float2 g_Bend[NCHUNK_*NCH_];
__device__ float2 g_Amat[NCHUNK_*NCH_];
__device__ float2 g_sinit[NCHUNK_*NCH_];
__device__ float g_h[T_*D_];
__device__ float g_ztmp[T_*D_];
// activations: exact fp16 pairs (hi+lo). weights: single fp16.
__device__ __half g_sclh[(size_t)T_*F_];
__device__ __half g_scll[(size_t)T_*F_];
__device__ __half g_w0h[L_*D_*F_];
__device__ __half g_w1h[L_*D_*D_];
__device__ __half g_wph[L_*128*D_];
__device__ __half g_z0h[T_*D_];
__device__ __half g_z0l[T_*D_];
__device__ __half g_xh[T_*D_];
__device__ __half g_xl[T_*D_];

// ---------------- low-level helpers (baseline PTX @ compute_103) ----------------
__device__ __forceinline__ uint32_t sptr(const void* p){
  return (uint32_t)__cvta_generic_to_shared(p);
}
__device__ __forceinline__ void cp16(uint32_t s, const void* g){
  asm volatile("cp.async.cg.shared.global [%0], [%1], 16;" :: "r"(s), "l"(g));
}
#define CP_COMMIT() asm volatile("cp.async.commit_group;" ::: "memory")
#define CP_WAIT(n)  asm volatile("cp.async.wait_group %0;" :: "n"(n) : "memory")

__device__ __forceinline__ void ldsm4(uint32_t* r, uint32_t a){
  asm volatile("ldmatrix.sync.aligned.m8n8.x4.shared.b16 {%0,%1,%2,%3}, [%4];"
    : "=r"(r[0]),"=r"(r[1]),"=r"(r[2]),"=r"(r[3]) : "r"(a));
}
__device__ __forceinline__ void mma_h(float* d, const uint32_t* a, const uint32_t* b){
  asm volatile("mma.sync.aligned.m16n8k16.row.col.f32.f16.f16.f32 "
    "{%0,%1,%2,%3}, {%4,%5,%6,%7}, {%8,%9}, {%0,%1,%2,%3};"
    : "+f"(d[0]),"+f"(d[1]),"+f"(d[2]),"+f"(d[3])
    : "r"(a[0]),"r"(a[1]),"r"(a[2]),"r"(a[3]), "r"(b[0]),"r"(b[1]));
}
__device__ __forceinline__ void emit2(float v, __half* h, __half* l){
  __half hh = __float2half_rn(v);
  *h = hh;
  *l = __float2half_rn(v - __half2float(hh));
}

// ---------------- prep kernels ----------------
__global__ void cvt_h(const float* __restrict__ src, __half* __restrict__ dst, int n){
  int i = blockIdx.x*blockDim.x + threadIdx.x;
  if (i < n) dst[i] = __float2half_rn(src[i]);
}

__global__ void copy_split_x(const float* __restrict__ src){
  int i = blockIdx.x*blockDim.x + threadIdx.x;
  float v = src[i];
  g_x[i] = v;
  emit2(v, g_xh+i, g_xl+i);
}

// stack Wtr(64xD), Wc(64xD) into 128xD fp16 weights
__global__ void prep_wproj(const float* __restrict__ Wtr, const float* __restrict__ Wc){
  int idx = blockIdx.x*blockDim.x + threadIdx.x;
  if (idx >= L_*128*D_) return;
  int l = idx / (128*D_);
  int rem = idx % (128*D_);
  int row = rem / D_, k = rem % D_;
  float v = (row < 64) ? Wtr[((size_t)l*64+row)*D_+k] : Wc[((size_t)l*64+row-64)*D_+k];
  g_wph[idx] = __float2half_rn(v);
}

// ================= 2-term fp16 GEMM: C[m,n] = sum_k (Ah+Al)[m,k]*Bh[n,k] =================
// BM=BN=128, BK=64, 256 threads (8 warps, 4x2), warp tile 32x64.
#define PADH 72                        // halves per SMEM row (64 data + 8 pad)
#define TILEH (128*PADH)               // halves per tile
#define STAGEH (3*TILEH)               // Ah, Al, Bh
#define GEMM_SMEM (2*STAGEH*2)         // bytes (2 stages) = 110592

__device__ __forceinline__ void stage_load2(
    __half* s, const __half* Ah, const __half* Al, const __half* Bh,
    int bm, int bn, int K, int k0, int tid)
{
  const __half* src[3] = {Ah, Al, Bh};
  #pragma unroll
  for (int t=0;t<3;t++){
    int rb = (t<2)? bm : bn;
    #pragma unroll
    for (int q=0;q<4;q++){
      int chunk = tid + q*256;          // 1024 16B-chunks per tile
      int row = chunk>>3, cc = chunk&7;
      uint32_t so = sptr(s + t*TILEH + row*PADH + cc*8);
      cp16(so, src[t] + (size_t)(rb+row)*K + k0 + cc*8);
    }
  }
}

__global__ void __launch_bounds__(256)
gemm2(const __half* __restrict__ Ah, const __half* __restrict__ Al,
      const __half* __restrict__ Bh, float* __restrict__ C, int K, int Nc)
{
  extern __shared__ __half smh[];
  const int tid = threadIdx.x;
  const int wid = tid>>5, lane = tid&31;
  const int bm = blockIdx.y*128, bn = blockIdx.x*128;
  const int wm = (wid>>1)*32;
  const int wn = (wid&1)*64;
  const int KT = K>>6;

  float acc[2][8][4];
  #pragma unroll
  for (int i=0;i<2;i++)
    #pragma unroll
    for (int j=0;j<8;j++)
      #pragma unroll
      for (int q=0;q<4;q++) acc[i][j][q]=0.f;

  stage_load2(smh, Ah, Al, Bh, bm, bn, K, 0, tid);
  CP_COMMIT();

  const int arow = lane & 15;
  const int acol8 = (lane>>4)*8;
  const int brow = (lane&7) + ((lane>>4)<<3);
  const int bsel = ((lane>>3)&1)*8;

  for (int c=0; c<KT; c++){
    if (c+1 < KT){
      stage_load2(smh + ((c+1)&1)*STAGEH, Ah, Al, Bh, bm, bn, K, (c+1)*64, tid);
      CP_COMMIT();
      CP_WAIT(1);
    } else {
      CP_WAIT(0);
    }
    __syncthreads();

    __half* s = smh + (c&1)*STAGEH;
    const uint32_t sAh = sptr(s);
    const uint32_t sAl = sAh + TILEH*2;
    const uint32_t sBh = sAh + 2*TILEH*2;

    #pragma unroll
    for (int ks=0; ks<4; ks++){
      uint32_t ah[2][4], al[2][4], bh[4][4];
      #pragma unroll
      for (int mi=0; mi<2; mi++){
        uint32_t off = (uint32_t)((wm + mi*16 + arow)*PADH + ks*16 + acol8)*2;
        ldsm4(ah[mi], sAh + off);
        ldsm4(al[mi], sAl + off);
      }
      #pragma unroll
      for (int p=0; p<4; p++){
        uint32_t off = (uint32_t)((wn + p*16 + brow)*PADH + ks*16 + bsel)*2;
        ldsm4(bh[p], sBh + off);
      }
      #pragma unroll
      for (int mi=0; mi<2; mi++)
        #pragma unroll
        for (int p=0; p<4; p++)
          #pragma unroll
          for (int h=0; h<2; h++){
            const int ni = p*2 + h;
            mma_h(acc[mi][ni], ah[mi], &bh[p][h*2]);
            mma_h(acc[mi][ni], al[mi], &bh[p][h*2]);
          }
    }
    __syncthreads();
  }

  #pragma unroll
  for (int mi=0; mi<2; mi++){
    const int r0 = bm + wm + mi*16 + (lane>>2);
    const int c0 = bn + wn + (lane&3)*2;
    #pragma unroll
    for (int ni=0; ni<8; ni++){
      *(float2*)(C + (size_t)r0*Nc + c0 + ni*8)     = make_float2(acc[mi][ni][0], acc[mi][ni][1]);
      *(float2*)(C + (size_t)(r0+8)*Nc + c0 + ni*8) = make_float2(acc[mi][ni][2], acc[mi][ni][3]);
    }
  }
}

// ---------------- u, v with normalization ----------------
__global__ void uv_kernel(){
  int t = blockIdx.x;
  int i = threadIdx.x;
  float uu = fabsf(g_trct[t*128 + i]);
  float vv = fabsf(g_trct[t*128 + 64 + i]);
  __shared__ float su[64], sv[64];
  su[i]=uu; sv[i]=vv; __syncthreads();
  for (int s=32; s>0; s>>=1){
    if (i<s){ su[i]+=su[i+s]; sv[i]+=sv[i+s]; }
    __syncthreads();
  }
  float scale = __fdividef(1.0f, 1e-8f + su[0]*sv[0]);
  g_u[t*TR_+i] = uu;
  g_v[t*CC_+i] = vv*scale;
}

__device__ __forceinline__ void make_decay(float ai, float bj, float& dre, float& dim){
  double rho = exp(-(double)fabsf(ai));
  double sb, cb; sincos((double)bj, &sb, &cb);
  dre = (float)(rho*cb); dim = (float)(rho*sb);
}

__global__ void scan_passA(const unsigned* __restrict__ start,
                           const float* __restrict__ a, const float* __restrict__ b,
                           int layer){
  const int i = blockIdx.y;
  const int c = blockIdx.x;
  const int j = threadIdx.x;
  const float ai = a[layer*TR_ + i];
  const float bj = b[layer*CC_ + j];
  float dre, dim;
  make_decay(ai, bj, dre, dim);
  float sre=0.f, sim=0.f;
  int reset = 0;
  const int t0 = c*CHUNK_;
  for (int t=t0; t<t0+CHUNK_; t++){
    if (start[t]){ sre=0.f; sim=0.f; reset=1; }
    float p = g_u[t*TR_+i]*g_v[t*CC_+j];
    float nre = fmaf(sre,dre, fmaf(-sim,dim,p));
    float nim = fmaf(sre,dim, sim*dre);
    sre=nre; sim=nim;
  }
  const int ch = i*CC_+j;
  g_Bend[c*NCH_+ch]=make_float2(sre,sim);
  float2 A;
  if (reset){ A=make_float2(0.f,0.f); }
  else {
    double rhoL = exp(-(double)fabsf(ai)*(double)CHUNK_);
    double sL,cL; sincos((double)bj*(double)CHUNK_, &sL,&cL);
    A = make_float2((float)(rhoL*cL), (float)(rhoL*sL));
  }
  g_Amat[c*NCH_+ch]=A;
}

__global__ void scan_passB(const float* __restrict__ state, int layer){
  int ch = blockIdx.x*blockDim.x + threadIdx.x;
  float sre = state[layer*NCH_ + ch];
  float sim = 0.f;
  #pragma unroll
  for (int c=0;c<NCHUNK_;c++){
    g_sinit[c*NCH_+ch] = make_float2(sre,sim);
    float2 A = g_Amat[c*NCH_+ch];
    float2 B = g_Bend[c*NCH_+ch];
    float nre = A.x*sre - A.y*sim + B.x;
    float nim = A.x*sim + A.y*sre + B.y;
    sre=nre; sim=nim;
  }
}

// full scan + feature emission as exact fp16 pairs
__global__ void scan_passC(const unsigned* __restrict__ start,
                           const float* __restrict__ a, const float* __restrict__ b,
                           int layer){
  const int i = blockIdx.y, c = blockIdx.x, j = threadIdx.x;
  float dre, dim;
  make_decay(a[layer*TR_+i], b[layer*CC_+j], dre, dim);
  const int ch = i*CC_+j;
  float2 s0 = g_sinit[c*NCH_+ch];
  float sre=s0.x, sim=s0.y;
  const int t0=c*CHUNK_;
  for (int t=t0;t<t0+CHUNK_;t++){
    if (start[t]){ sre=0.f; sim=0.f; }
    float p = g_u[t*TR_+i]*g_v[t*CC_+j];
    float nre = fmaf(sre,dre, fmaf(-sim,dim,p));
    float nim = fmaf(sre,dim, sim*dre);
    sre=nre; sim=nim;
    float r2 = fmaf(sre,sre, sim*sim);
    float f;
    if (r2 > 1e-24f){
      float rr = sqrtf(r2);
      f = __fdividef(log1pf(rr), rr);
    } else {
      f = 1.f;
    }
    float fs = f*sim, fc = f*sre;
    size_t o0 = (size_t)t*F_ + ch;
    size_t o1 = o0 + NCH_;
    emit2(fs, g_sclh+o0, g_scll+o0);
    emit2(fc, g_sclh+o1, g_scll+o1);
  }
}

// ================= LayerNorm + leaky ReLU =================
__device__ __forceinline__ void reduce2(float &s, float &ss){
  __shared__ float sh[8], sh2[8];
  int lane = threadIdx.x & 31, w = threadIdx.x >> 5;
  #pragma unroll
  for (int o=16;o>0;o>>=1){
    s  += __shfl_down_sync(0xffffffffu, s,  o);
    ss += __shfl_down_sync(0xffffffffu, ss, o);
  }
  if (lane==0){ sh[w]=s; sh2[w]=ss; }
  __syncthreads();
  if (w==0){
    s  = (lane<8)? sh[lane]  : 0.f;
    ss = (lane<8)? sh2[lane] : 0.f;
    #pragma unroll
    for (int o=4;o>0;o>>=1){
      s  += __shfl_down_sync(0xffffffffu, s,  o);
      ss += __shfl_down_sync(0xffffffffu, ss, o);
    }
    if (lane==0){ sh[0]=s; sh2[0]=ss; }
  }
  __syncthreads();
  s = sh[0]; ss = sh2[0];
}

__global__ void ln_leaky(const float* __restrict__ zin, const float* __restrict__ bias,
                         const float* __restrict__ gamma, const float* __restrict__ beta,
                         float* __restrict__ zout, float* __restrict__ xacc,
                         __half* __restrict__ zh, __half* __restrict__ zl,
                         __half* __restrict__ xh, __half* __restrict__ xl){
  const int t = blockIdx.x;
  const int tid = threadIdx.x;
  float v0 = zin[t*D_ + tid]       + bias[tid];
  float v1 = zin[t*D_ + 256 + tid] + bias[256+tid];
  float s = v0+v1;
  float ss = v0*v0 + v1*v1;
  reduce2(s, ss);
  float m = s * (1.f/512.f);
  float var = ss * (1.f/512.f) - m*m;
  float rinv = rsqrtf(var + 1e-5f);
  float y0 = (v0 - m)*rinv*gamma[tid]     + beta[tid];
  float y1 = (v1 - m)*rinv*gamma[256+tid] + beta[256+tid];
  y0 = (y0 > 0.f) ? y0 : 0.01f*y0;
  y1 = (y1 > 0.f) ? y1 : 0.01f*y1;
  if (zout){
    zout[t*D_ + tid]       = y0;
    zout[t*D_ + 256 + tid] = y1;
  }
  if (xacc){
    float x0 = xacc[t*D_ + tid]       + y0;
    float x1 = xacc[t*D_ + 256 + tid] + y1;
    xacc[t*D_ + tid]       = x0;
    xacc[t*D_ + 256 + tid] = x1;
    if (xh){
      emit2(x0, xh + t*D_ + tid,       xl + t*D_ + tid);
      emit2(x1, xh + t*D_ + 256 + tid, xl + t*D_ + 256 + tid);
    }
  }
  if (zh){
    emit2(y0, zh + t*D_ + tid,       zl + t*D_ + tid);
    emit2(y1, zh + t*D_ + 256 + tid, zl + t*D_ + 256 + tid);
  }
}

// ================= launcher =================
extern "C" void kernel_launch(void* const* d_in, const int* in_sizes, int n_in,
                              void* d_out, int out_size) {
  const float*    x     = (const float*)d_in[0];
  const float*    state = (const float*)d_in[1];
  const unsigned* start = (const unsigned*)d_in[2];
  const float*    Wtr   = (const float*)d_in[3];
  const float*    Wc    = (const float*)d_in[4];
  const float*    a     = (const float*)d_in[5];
  const float*    b     = (const float*)d_in[6];
  const float*    W0    = (const float*)d_in[7];
  const float*    b0    = (const float*)d_in[8];
  const float*    g0    = (const float*)d_in[9];
  const float*    beta0 = (const float*)d_in[10];
  const float*    W1    = (const float*)d_in[11];
  const float*    b1    = (const float*)d_in[12];
  const float*    g1    = (const float*)d_in[13];
  const float*    beta1 = (const float*)d_in[14];
  float* out = (float*)d_out;

  float *px, *ptrct, *ph, *pzt;
  __half *psh, *psl, *pw0h, *pw1h, *pwph, *pz0h, *pz0l, *pxh, *pxl;
  cudaGetSymbolAddress((void**)&px,    g_x);
  cudaGetSymbolAddress((void**)&ptrct, g_trct);
  cudaGetSymbolAddress((void**)&ph,    g_h);
  cudaGetSymbolAddress((void**)&pzt,   g_ztmp);
  cudaGetSymbolAddress((void**)&psh,   g_sclh);
  cudaGetSymbolAddress((void**)&psl,   g_scll);
  cudaGetSymbolAddress((void**)&pw0h,  g_w0h);
  cudaGetSymbolAddress((void**)&pw1h,  g_w1h);
  cudaGetSymbolAddress((void**)&pwph,  g_wph);
  cudaGetSymbolAddress((void**)&pz0h,  g_z0h);
  cudaGetSymbolAddress((void**)&pz0l,  g_z0l);
  cudaGetSymbolAddress((void**)&pxh,   g_xh);
  cudaGetSymbolAddress((void**)&pxl,   g_xl);

  cudaFuncSetAttribute(gemm2, cudaFuncAttributeMaxDynamicSharedMemorySize, GEMM_SMEM);

  copy_split_x<<<(T_*D_)/256, 256>>>(x);
  cvt_h<<<(L_*D_*F_ + 255)/256, 256>>>(W0, pw0h, L_*D_*F_);
  cvt_h<<<(L_*D_*D_ + 255)/256, 256>>>(W1, pw1h, L_*D_*D_);
  prep_wproj<<<(L_*128*D_ + 255)/256, 256>>>(Wtr, Wc);

  for (int l=0; l<L_; l++){
    // [tr|ct] = x @ [Wtr;Wc]^T  (M=4096, N=128, K=512)
    gemm2<<<dim3(1, T_/128), 256, GEMM_SMEM>>>(
        pxh, pxl, pwph + (size_t)l*128*D_, ptrct, D_, 128);
    uv_kernel<<<T_, 64>>>();

    scan_passA<<<dim3(NCHUNK_, TR_), CC_>>>(start, a, b, l);
    scan_passB<<<NCH_/256, 256>>>(state, l);
    scan_passC<<<dim3(NCHUNK_, TR_), CC_>>>(start, a, b, l);

    // h = scaled @ W0^T   (M=4096, N=512, K=8192)
    gemm2<<<dim3(D_/128, T_/128), 256, GEMM_SMEM>>>(
        psh, psl, pw0h + (size_t)l*D_*F_, ph, F_, D_);
    ln_leaky<<<T_, 256>>>(ph, b0 + l*D_, g0 + l*D_, beta0 + l*D_,
                          nullptr, nullptr, pz0h, pz0l, nullptr, nullptr);

    // h = z0 @ W1^T   (M=4096, N=512, K=512)
    gemm2<<<dim3(D_/128, T_/128), 256, GEMM_SMEM>>>(
        pz0h, pz0l, pw1h + (size_t)l*D_*D_, ph, D_, D_);
    float* zo = (l == L_-1) ? out : pzt;
    bool last = (l == L_-1);
    ln_leaky<<<T_, 256>>>(ph, b1 + l*D_, g1 + l*D_, beta1 + l*D_,
                          zo, px, nullptr, nullptr,
                          last ? nullptr : pxh, last ? nullptr : pxl);
  }
}

// round 7
// speedup vs baseline: 1.5496x; 1.0616x over previous
#include <cuda_runtime.h>
#include <cuda_fp16.h>
#include <math.h>
#include <stdint.h>

#define T_ 4096
#define D_ 512
#define TR_ 64
#define CC_ 64
#define L_ 3
#define F_ 8192
#define NCH_ 4096
#define NCHUNK_ 16
#define CHUNK_ 256

// ---------------- scratch ----------------
__device__ float g_x[T_*D_];
__device__ float g_u[T_*TR_];
__device__ float g_v[T_*CC_];
__device__ float2 g_Bend[NCHUNK_*NCH_];
__device__ float2 g_Amat[NCHUNK_*NCH_];
__device__ float2 g_sinit[NCHUNK_*NCH_];
__device__ float g_h[T_*D_];
__device__ float g_ztmp[T_*D_];
// activations: exact fp16 pairs (hi+lo). weights: single fp16.
__device__ __half g_sclh[(size_t)T_*F_];
__device__ __half g_scll[(size_t)T_*F_];
__device__ __half g_w0h[L_*D_*F_];
__device__ __half g_w1h[L_*D_*D_];
__device__ __half g_wph[L_*128*D_];
__device__ __half g_z0h[T_*D_];
__device__ __half g_z0l[T_*D_];
__device__ __half g_xh[T_*D_];
__device__ __half g_xl[T_*D_];

// ---------------- low-level helpers (baseline PTX @ compute_103) ----------------
__device__ __forceinline__ uint32_t sptr(const void* p){
  return (uint32_t)__cvta_generic_to_shared(p);
}
__device__ __forceinline__ void cp16(uint32_t s, const void* g){
  asm volatile("cp.async.cg.shared.global [%0], [%1], 16;" :: "r"(s), "l"(g));
}
#define CP_COMMIT() asm volatile("cp.async.commit_group;" ::: "memory")
#define CP_WAIT(n)  asm volatile("cp.async.wait_group %0;" :: "n"(n) : "memory")

__device__ __forceinline__ void ldsm4(uint32_t* r, uint32_t a){
  asm volatile("ldmatrix.sync.aligned.m8n8.x4.shared.b16 {%0,%1,%2,%3}, [%4];"
    : "=r"(r[0]),"=r"(r[1]),"=r"(r[2]),"=r"(r[3]) : "r"(a));
}
__device__ __forceinline__ void mma_h(float* d, const uint32_t* a, const uint32_t* b){
  asm volatile("mma.sync.aligned.m16n8k16.row.col.f32.f16.f16.f32 "
    "{%0,%1,%2,%3}, {%4,%5,%6,%7}, {%8,%9}, {%0,%1,%2,%3};"
    : "+f"(d[0]),"+f"(d[1]),"+f"(d[2]),"+f"(d[3])
    : "r"(a[0]),"r"(a[1]),"r"(a[2]),"r"(a[3]), "r"(b[0]),"r"(b[1]));
}
__device__ __forceinline__ void emit2(float v, __half* h, __half* l){
  __half hh = __float2half_rn(v);
  *h = hh;
  *l = __float2half_rn(v - __half2float(hh));
}

// ---------------- prep kernels ----------------
__global__ void cvt_h(const float* __restrict__ src, __half* __restrict__ dst, int n){
  int i = blockIdx.x*blockDim.x + threadIdx.x;
  if (i < n) dst[i] = __float2half_rn(src[i]);
}

__global__ void copy_split_x(const float* __restrict__ src){
  int i = blockIdx.x*blockDim.x + threadIdx.x;
  float v = src[i];
  g_x[i] = v;
  emit2(v, g_xh+i, g_xl+i);
}

__global__ void prep_wproj(const float* __restrict__ Wtr, const float* __restrict__ Wc){
  int idx = blockIdx.x*blockDim.x + threadIdx.x;
  if (idx >= L_*128*D_) return;
  int l = idx / (128*D_);
  int rem = idx % (128*D_);
  int row = rem / D_, k = rem % D_;
  float v = (row < 64) ? Wtr[((size_t)l*64+row)*D_+k] : Wc[((size_t)l*64+row-64)*D_+k];
  g_wph[idx] = __float2half_rn(v);
}

// ================= main 2-term fp16 GEMM (3-stage, 1 sync/iter) =================
// C[m,n] = sum_k (Ah+Al)[m,k]*Bh[n,k]. BM=BN=128, BK=64, 256 thr, warp tile 32x64.
#define PADH 72
#define TILEH (128*PADH)
#define STAGEH (3*TILEH)               // Ah, Al, Bh
#define GEMM_SMEM (3*STAGEH*2)         // 3 stages = 165888 B

__device__ __forceinline__ void stage_load2(
    __half* s, const __half* Ah, const __half* Al, const __half* Bh,
    int bm, int bn, int K, int k0, int tid)
{
  const __half* src[3] = {Ah, Al, Bh};
  #pragma unroll
  for (int t=0;t<3;t++){
    int rb = (t<2)? bm : bn;
    #pragma unroll
    for (int q=0;q<4;q++){
      int chunk = tid + q*256;
      int row = chunk>>3, cc = chunk&7;
      uint32_t so = sptr(s + t*TILEH + row*PADH + cc*8);
      cp16(so, src[t] + (size_t)(rb+row)*K + k0 + cc*8);
    }
  }
}

__global__ void __launch_bounds__(256)
gemm2(const __half* __restrict__ Ah, const __half* __restrict__ Al,
      const __half* __restrict__ Bh, float* __restrict__ C, int K, int Nc)
{
  extern __shared__ __half smh[];
  const int tid = threadIdx.x;
  const int wid = tid>>5, lane = tid&31;
  const int bm = blockIdx.y*128, bn = blockIdx.x*128;
  const int wm = (wid>>1)*32;
  const int wn = (wid&1)*64;
  const int KT = K>>6;

  float acc[2][8][4];
  #pragma unroll
  for (int i=0;i<2;i++)
    #pragma unroll
    for (int j=0;j<8;j++)
      #pragma unroll
      for (int q=0;q<4;q++) acc[i][j][q]=0.f;

  stage_load2(smh, Ah, Al, Bh, bm, bn, K, 0, tid);
  CP_COMMIT();
  if (KT > 1){
    stage_load2(smh + STAGEH, Ah, Al, Bh, bm, bn, K, 64, tid);
    CP_COMMIT();
  }

  const int arow = lane & 15;
  const int acol8 = (lane>>4)*8;
  const int brow = (lane&7) + ((lane>>4)<<3);
  const int bsel = ((lane>>3)&1)*8;

  int bufc = 0;
  for (int c=0; c<KT; c++){
    if (c+1 < KT) { CP_WAIT(1); } else { CP_WAIT(0); }
    __syncthreads();

    __half* s = smh + bufc*STAGEH;
    const uint32_t sAh = sptr(s);
    const uint32_t sAl = sAh + TILEH*2;
    const uint32_t sBh = sAh + 2*TILEH*2;

    #pragma unroll
    for (int ks=0; ks<4; ks++){
      uint32_t ah[2][4], al[2][4], bh[4][4];
      #pragma unroll
      for (int mi=0; mi<2; mi++){
        uint32_t off = (uint32_t)((wm + mi*16 + arow)*PADH + ks*16 + acol8)*2;
        ldsm4(ah[mi], sAh + off);
        ldsm4(al[mi], sAl + off);
      }
      #pragma unroll
      for (int p=0; p<4; p++){
        uint32_t off = (uint32_t)((wn + p*16 + brow)*PADH + ks*16 + bsel)*2;
        ldsm4(bh[p], sBh + off);
      }
      #pragma unroll
      for (int mi=0; mi<2; mi++)
        #pragma unroll
        for (int p=0; p<4; p++)
          #pragma unroll
          for (int h=0; h<2; h++){
            const int ni = p*2 + h;
            mma_h(acc[mi][ni], ah[mi], &bh[p][h*2]);
            mma_h(acc[mi][ni], al[mi], &bh[p][h*2]);
          }
    }

    if (c+2 < KT){
      int buf2 = bufc + 2; if (buf2 >= 3) buf2 -= 3;
      stage_load2(smh + buf2*STAGEH, Ah, Al, Bh, bm, bn, K, (c+2)*64, tid);
      CP_COMMIT();
    }
    bufc++; if (bufc == 3) bufc = 0;
  }

  #pragma unroll
  for (int mi=0; mi<2; mi++){
    const int r0 = bm + wm + mi*16 + (lane>>2);
    const int c0 = bn + wn + (lane&3)*2;
    #pragma unroll
    for (int ni=0; ni<8; ni++){
      *(float2*)(C + (size_t)r0*Nc + c0 + ni*8)     = make_float2(acc[mi][ni][0], acc[mi][ni][1]);
      *(float2*)(C + (size_t)(r0+8)*Nc + c0 + ni*8) = make_float2(acc[mi][ni][2], acc[mi][ni][3]);
    }
  }
}

// ================= fused projection + uv =================
// [tr|ct](64 rows/CTA x 128 cols) = x @ [Wtr;Wc]^T, then per row t:
//   u[t,i] = |tr_i| ; v[t,j] = |ct_j| / (1e-8 + sum|tr| * sum|ct|)
// BM=64, BN=128, K=512, 256 threads, warp tile 32x32 (2x4 warps).
#define PPADH 72
#define PA_TILE (64*PPADH)
#define PB_TILE (128*PPADH)
#define PSTAGE (2*PA_TILE + PB_TILE)
#define PROJ_SMEM (2*PSTAGE*2)          // 73728 B

__device__ __forceinline__ void stage_load_proj(
    __half* s, const __half* Ah, const __half* Al, const __half* Bh,
    int bm, int K, int k0, int tid)
{
  // A tensors: 64 rows -> 512 chunks each; B: 128 rows -> 1024 chunks
  #pragma unroll
  for (int q=0;q<2;q++){
    int chunk = tid + q*256;
    int row = chunk>>3, cc = chunk&7;
    uint32_t so = sptr(s + row*PPADH + cc*8);
    cp16(so, Ah + (size_t)(bm+row)*K + k0 + cc*8);
    uint32_t so2 = sptr(s + PA_TILE + row*PPADH + cc*8);
    cp16(so2, Al + (size_t)(bm+row)*K + k0 + cc*8);
  }
  #pragma unroll
  for (int q=0;q<4;q++){
    int chunk = tid + q*256;
    int row = chunk>>3, cc = chunk&7;
    uint32_t so = sptr(s + 2*PA_TILE + row*PPADH + cc*8);
    cp16(so, Bh + (size_t)row*K + k0 + cc*8);
  }
}

__global__ void __launch_bounds__(256)
proj_uv(const __half* __restrict__ Ah, const __half* __restrict__ Al,
        const __half* __restrict__ Bh)
{
  extern __shared__ __half smh[];
  __shared__ float ssum[4][64];
  __shared__ float sscale[64];
  const int tid = threadIdx.x;
  const int wid = tid>>5, lane = tid&31;
  const int bm = blockIdx.y*64;
  const int wm = (wid&1)*32;
  const int wn = (wid>>1)*32;
  const int K = D_;
  const int KT = K>>6;      // 8

  float acc[2][4][4];
  #pragma unroll
  for (int i=0;i<2;i++)
    #pragma unroll
    for (int j=0;j<4;j++)
      #pragma unroll
      for (int q=0;q<4;q++) acc[i][j][q]=0.f;

  stage_load_proj(smh, Ah, Al, Bh, bm, K, 0, tid);
  CP_COMMIT();

  const int arow = lane & 15;
  const int acol8 = (lane>>4)*8;
  const int brow = (lane&7) + ((lane>>4)<<3);
  const int bsel = ((lane>>3)&1)*8;

  for (int c=0; c<KT; c++){
    if (c+1 < KT){
      stage_load_proj(smh + ((c+1)&1)*PSTAGE, Ah, Al, Bh, bm, K, (c+1)*64, tid);
      CP_COMMIT();
      CP_WAIT(1);
    } else {
      CP_WAIT(0);
    }
    __syncthreads();

    __half* s = smh + (c&1)*PSTAGE;
    const uint32_t sAh = sptr(s);
    const uint32_t sAl = sAh + PA_TILE*2;
    const uint32_t sBh = sAh + 2*PA_TILE*2;

    #pragma unroll
    for (int ks=0; ks<4; ks++){
      uint32_t ah[2][4], al[2][4], bh[2][4];
      #pragma unroll
      for (int mi=0; mi<2; mi++){
        uint32_t off = (uint32_t)((wm + mi*16 + arow)*PPADH + ks*16 + acol8)*2;
        ldsm4(ah[mi], sAh + off);
        ldsm4(al[mi], sAl + off);
      }
      #pragma unroll
      for (int p=0; p<2; p++){
        uint32_t off = (uint32_t)((wn + p*16 + brow)*PPADH + ks*16 + bsel)*2;
        ldsm4(bh[p], sBh + off);
      }
      #pragma unroll
      for (int mi=0; mi<2; mi++)
        #pragma unroll
        for (int p=0; p<2; p++)
          #pragma unroll
          for (int h=0; h<2; h++){
            const int ni = p*2 + h;
            mma_h(acc[mi][ni], ah[mi], &bh[p][h*2]);
            mma_h(acc[mi][ni], al[mi], &bh[p][h*2]);
          }
    }
    __syncthreads();
  }

  // ---- fused uv epilogue ----
  const int colblk = wid>>1;
  #pragma unroll
  for (int mi=0; mi<2; mi++){
    #pragma unroll
    for (int qh=0; qh<2; qh++){
      float sv = 0.f;
      #pragma unroll
      for (int ni=0; ni<4; ni++)
        sv += fabsf(acc[mi][ni][qh*2]) + fabsf(acc[mi][ni][qh*2+1]);
      sv += __shfl_xor_sync(0xffffffffu, sv, 1);
      sv += __shfl_xor_sync(0xffffffffu, sv, 2);
      if ((lane&3)==0)
        ssum[colblk][wm + mi*16 + qh*8 + (lane>>2)] = sv;
    }
  }
  __syncthreads();
  if (tid < 64){
    float str = ssum[0][tid] + ssum[1][tid];
    float sct = ssum[2][tid] + ssum[3][tid];
    sscale[tid] = __fdividef(1.f, 1e-8f + str*sct);
  }
  __syncthreads();
  #pragma unroll
  for (int mi=0; mi<2; mi++){
    #pragma unroll
    for (int ni=0; ni<4; ni++){
      #pragma unroll
      for (int q=0; q<4; q++){
        int rloc = wm + mi*16 + (q>>1)*8 + (lane>>2);
        int t = bm + rloc;
        int col = wn + (lane&3)*2 + ni*8 + (q&1);
        float vabs = fabsf(acc[mi][ni][q]);
        if (col < 64) g_u[t*TR_ + col] = vabs;
        else          g_v[t*CC_ + col - 64] = vabs * sscale[rloc];
      }
    }
  }
}

// ---------------- scan ----------------
__device__ __forceinline__ void make_decay(float ai, float bj, float& dre, float& dim){
  double rho = exp(-(double)fabsf(ai));
  double sb, cb; sincos((double)bj, &sb, &cb);
  dre = (float)(rho*cb); dim = (float)(rho*sb);
}

__global__ void scan_passA(const unsigned* __restrict__ start,
                           const float* __restrict__ a, const float* __restrict__ b,
                           int layer){
  const int i = blockIdx.y;
  const int c = blockIdx.x;
  const int j = threadIdx.x;
  const float ai = a[layer*TR_ + i];
  const float bj = b[layer*CC_ + j];
  float dre, dim;
  make_decay(ai, bj, dre, dim);
  float sre=0.f, sim=0.f;
  int reset = 0;
  const int t0 = c*CHUNK_;
  for (int t=t0; t<t0+CHUNK_; t++){
    if (start[t]){ sre=0.f; sim=0.f; reset=1; }
    float p = g_u[t*TR_+i]*g_v[t*CC_+j];
    float nre = fmaf(sre,dre, fmaf(-sim,dim,p));
    float nim = fmaf(sre,dim, sim*dre);
    sre=nre; sim=nim;
  }
  const int ch = i*CC_+j;
  g_Bend[c*NCH_+ch]=make_float2(sre,sim);
  float2 A;
  if (reset){ A=make_float2(0.f,0.f); }
  else {
    double rhoL = exp(-(double)fabsf(ai)*(double)CHUNK_);
    double sL,cL; sincos((double)bj*(double)CHUNK_, &sL,&cL);
    A = make_float2((float)(rhoL*cL), (float)(rhoL*sL));
  }
  g_Amat[c*NCH_+ch]=A;
}

__global__ void scan_passB(const float* __restrict__ state, int layer){
  int ch = blockIdx.x*blockDim.x + threadIdx.x;
  float sre = state[layer*NCH_ + ch];
  float sim = 0.f;
  #pragma unroll
  for (int c=0;c<NCHUNK_;c++){
    g_sinit[c*NCH_+ch] = make_float2(sre,sim);
    float2 A = g_Amat[c*NCH_+ch];
    float2 B = g_Bend[c*NCH_+ch];
    float nre = A.x*sre - A.y*sim + B.x;
    float nim = A.x*sim + A.y*sre + B.y;
    sre=nre; sim=nim;
  }
}

__global__ void scan_passC(const unsigned* __restrict__ start,
                           const float* __restrict__ a, const float* __restrict__ b,
                           int layer){
  const int i = blockIdx.y, c = blockIdx.x, j = threadIdx.x;
  float dre, dim;
  make_decay(a[layer*TR_+i], b[layer*CC_+j], dre, dim);
  const int ch = i*CC_+j;
  float2 s0 = g_sinit[c*NCH_+ch];
  float sre=s0.x, sim=s0.y;
  const int t0=c*CHUNK_;
  for (int t=t0;t<t0+CHUNK_;t++){
    if (start[t]){ sre=0.f; sim=0.f; }
    float p = g_u[t*TR_+i]*g_v[t*CC_+j];
    float nre = fmaf(sre,dre, fmaf(-sim,dim,p));
    float nim = fmaf(sre,dim, sim*dre);
    sre=nre; sim=nim;
    float r2 = fmaf(sre,sre, sim*sim);
    float f;
    if (r2 > 1e-24f){
      float rr = sqrtf(r2);
      f = __fdividef(log1pf(rr), rr);
    } else {
      f = 1.f;
    }
    float fs = f*sim, fc = f*sre;
    size_t o0 = (size_t)t*F_ + ch;
    size_t o1 = o0 + NCH_;
    emit2(fs, g_sclh+o0, g_scll+o0);
    emit2(fc, g_sclh+o1, g_scll+o1);
  }
}

// ================= LayerNorm + leaky ReLU =================
__device__ __forceinline__ void reduce2(float &s, float &ss){
  __shared__ float sh[8], sh2[8];
  int lane = threadIdx.x & 31, w = threadIdx.x >> 5;
  #pragma unroll
  for (int o=16;o>0;o>>=1){
    s  += __shfl_down_sync(0xffffffffu, s,  o);
    ss += __shfl_down_sync(0xffffffffu, ss, o);
  }
  if (lane==0){ sh[w]=s; sh2[w]=ss; }
  __syncthreads();
  if (w==0){
    s  = (lane<8)? sh[lane]  : 0.f;
    ss = (lane<8)? sh2[lane] : 0.f;
    #pragma unroll
    for (int o=4;o>0;o>>=1){
      s  += __shfl_down_sync(0xffffffffu, s,  o);
      ss += __shfl_down_sync(0xffffffffu, ss, o);
    }
    if (lane==0){ sh[0]=s; sh2[0]=ss; }
  }
  __syncthreads();
  s = sh[0]; ss = sh2[0];
}

__global__ void ln_leaky(const float* __restrict__ zin, const float* __restrict__ bias,
                         const float* __restrict__ gamma, const float* __restrict__ beta,
                         float* __restrict__ zout, float* __restrict__ xacc,
                         __half* __restrict__ zh, __half* __restrict__ zl,
                         __half* __restrict__ xh, __half* __restrict__ xl){
  const int t = blockIdx.x;
  const int tid = threadIdx.x;
  float v0 = zin[t*D_ + tid]       + bias[tid];
  float v1 = zin[t*D_ + 256 + tid] + bias[256+tid];
  float s = v0+v1;
  float ss = v0*v0 + v1*v1;
  reduce2(s, ss);
  float m = s * (1.f/512.f);
  float var = ss * (1.f/512.f) - m*m;
  float rinv = rsqrtf(var + 1e-5f);
  float y0 = (v0 - m)*rinv*gamma[tid]     + beta[tid];
  float y1 = (v1 - m)*rinv*gamma[256+tid] + beta[256+tid];
  y0 = (y0 > 0.f) ? y0 : 0.01f*y0;
  y1 = (y1 > 0.f) ? y1 : 0.01f*y1;
  if (zout){
    zout[t*D_ + tid]       = y0;
    zout[t*D_ + 256 + tid] = y1;
  }
  if (xacc){
    float x0 = xacc[t*D_ + tid]       + y0;
    float x1 = xacc[t*D_ + 256 + tid] + y1;
    xacc[t*D_ + tid]       = x0;
    xacc[t*D_ + 256 + tid] = x1;
    if (xh){
      emit2(x0, xh + t*D_ + tid,       xl + t*D_ + tid);
      emit2(x1, xh + t*D_ + 256 + tid, xl + t*D_ + 256 + tid);
    }
  }
  if (zh){
    emit2(y0, zh + t*D_ + tid,       zl + t*D_ + tid);
    emit2(y1, zh + t*D_ + 256 + tid, zl + t*D_ + 256 + tid);
  }
}

// ================= launcher =================
extern "C" void kernel_launch(void* const* d_in, const int* in_sizes, int n_in,
                              void* d_out, int out_size) {
  const float*    x     = (const float*)d_in[0];
  const float*    state = (const float*)d_in[1];
  const unsigned* start = (const unsigned*)d_in[2];
  const float*    Wtr   = (const float*)d_in[3];
  const float*    Wc    = (const float*)d_in[4];
  const float*    a     = (const float*)d_in[5];
  const float*    b     = (const float*)d_in[6];
  const float*    W0    = (const float*)d_in[7];
  const float*    b0    = (const float*)d_in[8];
  const float*    g0    = (const float*)d_in[9];
  const float*    beta0 = (const float*)d_in[10];
  const float*    W1    = (const float*)d_in[11];
  const float*    b1    = (const float*)d_in[12];
  const float*    g1    = (const float*)d_in[13];
  const float*    beta1 = (const float*)d_in[14];
  float* out = (float*)d_out;

  float *px, *ph, *pzt;
  __half *psh, *psl, *pw0h, *pw1h, *pwph, *pz0h, *pz0l, *pxh, *pxl;
  cudaGetSymbolAddress((void**)&px,    g_x);
  cudaGetSymbolAddress((void**)&ph,    g_h);
  cudaGetSymbolAddress((void**)&pzt,   g_ztmp);
  cudaGetSymbolAddress((void**)&psh,   g_sclh);
  cudaGetSymbolAddress((void**)&psl,   g_scll);
  cudaGetSymbolAddress((void**)&pw0h,  g_w0h);
  cudaGetSymbolAddress((void**)&pw1h,  g_w1h);
  cudaGetSymbolAddress((void**)&pwph,  g_wph);
  cudaGetSymbolAddress((void**)&pz0h,  g_z0h);
  cudaGetSymbolAddress((void**)&pz0l,  g_z0l);
  cudaGetSymbolAddress((void**)&pxh,   g_xh);
  cudaGetSymbolAddress((void**)&pxl,   g_xl);

  cudaFuncSetAttribute(gemm2,   cudaFuncAttributeMaxDynamicSharedMemorySize, GEMM_SMEM);
  cudaFuncSetAttribute(proj_uv, cudaFuncAttributeMaxDynamicSharedMemorySize, PROJ_SMEM);

  copy_split_x<<<(T_*D_)/256, 256>>>(x);
  cvt_h<<<(L_*D_*F_ + 255)/256, 256>>>(W0, pw0h, L_*D_*F_);
  cvt_h<<<(L_*D_*D_ + 255)/256, 256>>>(W1, pw1h, L_*D_*D_);
  prep_wproj<<<(L_*128*D_ + 255)/256, 256>>>(Wtr, Wc);

  for (int l=0; l<L_; l++){
    // fused projection + uv (writes g_u, g_v directly)
    proj_uv<<<dim3(1, T_/64), 256, PROJ_SMEM>>>(pxh, pxl, pwph + (size_t)l*128*D_);

    scan_passA<<<dim3(NCHUNK_, TR_), CC_>>>(start, a, b, l);
    scan_passB<<<NCH_/256, 256>>>(state, l);
    scan_passC<<<dim3(NCHUNK_, TR_), CC_>>>(start, a, b, l);

    // h = scaled @ W0^T   (M=4096, N=512, K=8192)
    gemm2<<<dim3(D_/128, T_/128), 256, GEMM_SMEM>>>(
        psh, psl, pw0h + (size_t)l*D_*F_, ph, F_, D_);
    ln_leaky<<<T_, 256>>>(ph, b0 + l*D_, g0 + l*D_, beta0 + l*D_,
                          nullptr, nullptr, pz0h, pz0l, nullptr, nullptr);

    // h = z0 @ W1^T   (M=4096, N=512, K=512)
    gemm2<<<dim3(D_/128, T_/128), 256, GEMM_SMEM>>>(
        pz0h, pz0l, pw1h + (size_t)l*D_*D_, ph, D_, D_);
    float* zo = (l == L_-1) ? out : pzt;
    bool last = (l == L_-1);
    ln_leaky<<<T_, 256>>>(ph, b1 + l*D_, g1 + l*D_, beta1 + l*D_,
                          zo, px, nullptr, nullptr,
                          last ? nullptr : pxh, last ? nullptr : pxl);
  }
}

// round 8
// speedup vs baseline: 2.1857x; 1.4105x over previous
#include <cuda_runtime.h>
#include <cuda_fp16.h>
#include <math.h>
#include <stdint.h>

#define T_ 4096
#define D_ 512
#define TR_ 64
#define CC_ 64
#define L_ 3
#define F_ 8192
#define NCH_ 4096
#define NCHUNK_ 16
#define CHUNK_ 256

// ---------------- scratch ----------------
__device__ float g_x[T_*D_];
__device__ float g_u[T_*TR_];
__device__ float g_v[T_*CC_];
__device__ float2 g_Bend[NCHUNK_*NCH_];
__device__ float2 g_Amat[NCHUNK_*NCH_];
__device__ float2 g_sinit[NCHUNK_*NCH_];
__device__ float g_h[T_*D_];
__device__ float g_ztmp[T_*D_];
// features: single fp16 (1-term GEMM). activations x/z0: exact fp16 pairs.
__device__ __half g_sclh[(size_t)T_*F_];
__device__ __half g_w0h[L_*D_*F_];
__device__ __half g_w1h[L_*D_*D_];
__device__ __half g_wph[L_*128*D_];
__device__ __half g_z0h[T_*D_];
__device__ __half g_z0l[T_*D_];
__device__ __half g_xh[T_*D_];
__device__ __half g_xl[T_*D_];

// ---------------- low-level helpers (baseline PTX @ compute_103) ----------------
__device__ __forceinline__ uint32_t sptr(const void* p){
  return (uint32_t)__cvta_generic_to_shared(p);
}
__device__ __forceinline__ void cp16(uint32_t s, const void* g){
  asm volatile("cp.async.cg.shared.global [%0], [%1], 16;" :: "r"(s), "l"(g));
}
#define CP_COMMIT() asm volatile("cp.async.commit_group;" ::: "memory")
#define CP_WAIT(n)  asm volatile("cp.async.wait_group %0;" :: "n"(n) : "memory")

__device__ __forceinline__ void ldsm4(uint32_t* r, uint32_t a){
  asm volatile("ldmatrix.sync.aligned.m8n8.x4.shared.b16 {%0,%1,%2,%3}, [%4];"
    : "=r"(r[0]),"=r"(r[1]),"=r"(r[2]),"=r"(r[3]) : "r"(a));
}
__device__ __forceinline__ void mma_h(float* d, const uint32_t* a, const uint32_t* b){
  asm volatile("mma.sync.aligned.m16n8k16.row.col.f32.f16.f16.f32 "
    "{%0,%1,%2,%3}, {%4,%5,%6,%7}, {%8,%9}, {%0,%1,%2,%3};"
    : "+f"(d[0]),"+f"(d[1]),"+f"(d[2]),"+f"(d[3])
    : "r"(a[0]),"r"(a[1]),"r"(a[2]),"r"(a[3]), "r"(b[0]),"r"(b[1]));
}
__device__ __forceinline__ void emit2(float v, __half* h, __half* l){
  __half hh = __float2half_rn(v);
  *h = hh;
  *l = __float2half_rn(v - __half2float(hh));
}

// ---------------- prep kernels ----------------
__global__ void cvt_h(const float* __restrict__ src, __half* __restrict__ dst, int n){
  int i = blockIdx.x*blockDim.x + threadIdx.x;
  if (i < n) dst[i] = __float2half_rn(src[i]);
}

__global__ void copy_split_x(const float* __restrict__ src){
  int i = blockIdx.x*blockDim.x + threadIdx.x;
  float v = src[i];
  g_x[i] = v;
  emit2(v, g_xh+i, g_xl+i);
}

__global__ void prep_wproj(const float* __restrict__ Wtr, const float* __restrict__ Wc){
  int idx = blockIdx.x*blockDim.x + threadIdx.x;
  if (idx >= L_*128*D_) return;
  int l = idx / (128*D_);
  int rem = idx % (128*D_);
  int row = rem / D_, k = rem % D_;
  float v = (row < 64) ? Wtr[((size_t)l*64+row)*D_+k] : Wc[((size_t)l*64+row-64)*D_+k];
  g_wph[idx] = __float2half_rn(v);
}

#define PADH 72
#define TILEH (128*PADH)

// ================= 1-term fp16 GEMM (W0): C = Ah @ Bh^T, 3-stage =================
#define STAGE1 (2*TILEH)               // Ah, Bh
#define GEMM1_SMEM (3*STAGE1*2)        // 110592 B

__device__ __forceinline__ void stage_load1(
    __half* s, const __half* Ah, const __half* Bh,
    int bm, int bn, int K, int k0, int tid)
{
  const __half* src[2] = {Ah, Bh};
  #pragma unroll
  for (int t=0;t<2;t++){
    int rb = (t==0)? bm : bn;
    #pragma unroll
    for (int q=0;q<4;q++){
      int chunk = tid + q*256;
      int row = chunk>>3, cc = chunk&7;
      uint32_t so = sptr(s + t*TILEH + row*PADH + cc*8);
      cp16(so, src[t] + (size_t)(rb+row)*K + k0 + cc*8);
    }
  }
}

__global__ void __launch_bounds__(256)
gemm1(const __half* __restrict__ Ah, const __half* __restrict__ Bh,
      float* __restrict__ C, int K, int Nc)
{
  extern __shared__ __half smh[];
  const int tid = threadIdx.x;
  const int wid = tid>>5, lane = tid&31;
  const int bm = blockIdx.y*128, bn = blockIdx.x*128;
  const int wm = (wid>>1)*32;
  const int wn = (wid&1)*64;
  const int KT = K>>6;

  float acc[2][8][4];
  #pragma unroll
  for (int i=0;i<2;i++)
    #pragma unroll
    for (int j=0;j<8;j++)
      #pragma unroll
      for (int q=0;q<4;q++) acc[i][j][q]=0.f;

  stage_load1(smh, Ah, Bh, bm, bn, K, 0, tid);
  CP_COMMIT();
  if (KT > 1){
    stage_load1(smh + STAGE1, Ah, Bh, bm, bn, K, 64, tid);
    CP_COMMIT();
  }

  const int arow = lane & 15;
  const int acol8 = (lane>>4)*8;
  const int brow = (lane&7) + ((lane>>4)<<3);
  const int bsel = ((lane>>3)&1)*8;

  int bufc = 0;
  for (int c=0; c<KT; c++){
    if (c+1 < KT) { CP_WAIT(1); } else { CP_WAIT(0); }
    __syncthreads();

    __half* s = smh + bufc*STAGE1;
    const uint32_t sAh = sptr(s);
    const uint32_t sBh = sAh + TILEH*2;

    #pragma unroll
    for (int ks=0; ks<4; ks++){
      uint32_t ah[2][4], bh[4][4];
      #pragma unroll
      for (int mi=0; mi<2; mi++){
        uint32_t off = (uint32_t)((wm + mi*16 + arow)*PADH + ks*16 + acol8)*2;
        ldsm4(ah[mi], sAh + off);
      }
      #pragma unroll
      for (int p=0; p<4; p++){
        uint32_t off = (uint32_t)((wn + p*16 + brow)*PADH + ks*16 + bsel)*2;
        ldsm4(bh[p], sBh + off);
      }
      #pragma unroll
      for (int mi=0; mi<2; mi++)
        #pragma unroll
        for (int p=0; p<4; p++)
          #pragma unroll
          for (int h=0; h<2; h++)
            mma_h(acc[mi][p*2+h], ah[mi], &bh[p][h*2]);
    }

    if (c+2 < KT){
      int buf2 = bufc + 2; if (buf2 >= 3) buf2 -= 3;
      stage_load1(smh + buf2*STAGE1, Ah, Bh, bm, bn, K, (c+2)*64, tid);
      CP_COMMIT();
    }
    bufc++; if (bufc == 3) bufc = 0;
  }

  #pragma unroll
  for (int mi=0; mi<2; mi++){
    const int r0 = bm + wm + mi*16 + (lane>>2);
    const int c0 = bn + wn + (lane&3)*2;
    #pragma unroll
    for (int ni=0; ni<8; ni++){
      *(float2*)(C + (size_t)r0*Nc + c0 + ni*8)     = make_float2(acc[mi][ni][0], acc[mi][ni][1]);
      *(float2*)(C + (size_t)(r0+8)*Nc + c0 + ni*8) = make_float2(acc[mi][ni][2], acc[mi][ni][3]);
    }
  }
}

// ================= 2-term fp16 GEMM (W1): C = (Ah+Al) @ Bh^T, 3-stage =================
#define STAGEH (3*TILEH)               // Ah, Al, Bh
#define GEMM_SMEM (3*STAGEH*2)         // 165888 B

__device__ __forceinline__ void stage_load2(
    __half* s, const __half* Ah, const __half* Al, const __half* Bh,
    int bm, int bn, int K, int k0, int tid)
{
  const __half* src[3] = {Ah, Al, Bh};
  #pragma unroll
  for (int t=0;t<3;t++){
    int rb = (t<2)? bm : bn;
    #pragma unroll
    for (int q=0;q<4;q++){
      int chunk = tid + q*256;
      int row = chunk>>3, cc = chunk&7;
      uint32_t so = sptr(s + t*TILEH + row*PADH + cc*8);
      cp16(so, src[t] + (size_t)(rb+row)*K + k0 + cc*8);
    }
  }
}

__global__ void __launch_bounds__(256)
gemm2(const __half* __restrict__ Ah, const __half* __restrict__ Al,
      const __half* __restrict__ Bh, float* __restrict__ C, int K, int Nc)
{
  extern __shared__ __half smh[];
  const int tid = threadIdx.x;
  const int wid = tid>>5, lane = tid&31;
  const int bm = blockIdx.y*128, bn = blockIdx.x*128;
  const int wm = (wid>>1)*32;
  const int wn = (wid&1)*64;
  const int KT = K>>6;

  float acc[2][8][4];
  #pragma unroll
  for (int i=0;i<2;i++)
    #pragma unroll
    for (int j=0;j<8;j++)
      #pragma unroll
      for (int q=0;q<4;q++) acc[i][j][q]=0.f;

  stage_load2(smh, Ah, Al, Bh, bm, bn, K, 0, tid);
  CP_COMMIT();
  if (KT > 1){
    stage_load2(smh + STAGEH, Ah, Al, Bh, bm, bn, K, 64, tid);
    CP_COMMIT();
  }

  const int arow = lane & 15;
  const int acol8 = (lane>>4)*8;
  const int brow = (lane&7) + ((lane>>4)<<3);
  const int bsel = ((lane>>3)&1)*8;

  int bufc = 0;
  for (int c=0; c<KT; c++){
    if (c+1 < KT) { CP_WAIT(1); } else { CP_WAIT(0); }
    __syncthreads();

    __half* s = smh + bufc*STAGEH;
    const uint32_t sAh = sptr(s);
    const uint32_t sAl = sAh + TILEH*2;
    const uint32_t sBh = sAh + 2*TILEH*2;

    #pragma unroll
    for (int ks=0; ks<4; ks++){
      uint32_t ah[2][4], al[2][4], bh[4][4];
      #pragma unroll
      for (int mi=0; mi<2; mi++){
        uint32_t off = (uint32_t)((wm + mi*16 + arow)*PADH + ks*16 + acol8)*2;
        ldsm4(ah[mi], sAh + off);
        ldsm4(al[mi], sAl + off);
      }
      #pragma unroll
      for (int p=0; p<4; p++){
        uint32_t off = (uint32_t)((wn + p*16 + brow)*PADH + ks*16 + bsel)*2;
        ldsm4(bh[p], sBh + off);
      }
      #pragma unroll
      for (int mi=0; mi<2; mi++)
        #pragma unroll
        for (int p=0; p<4; p++)
          #pragma unroll
          for (int h=0; h<2; h++){
            const int ni = p*2 + h;
            mma_h(acc[mi][ni], ah[mi], &bh[p][h*2]);
            mma_h(acc[mi][ni], al[mi], &bh[p][h*2]);
          }
    }

    if (c+2 < KT){
      int buf2 = bufc + 2; if (buf2 >= 3) buf2 -= 3;
      stage_load2(smh + buf2*STAGEH, Ah, Al, Bh, bm, bn, K, (c+2)*64, tid);
      CP_COMMIT();
    }
    bufc++; if (bufc == 3) bufc = 0;
  }

  #pragma unroll
  for (int mi=0; mi<2; mi++){
    const int r0 = bm + wm + mi*16 + (lane>>2);
    const int c0 = bn + wn + (lane&3)*2;
    #pragma unroll
    for (int ni=0; ni<8; ni++){
      *(float2*)(C + (size_t)r0*Nc + c0 + ni*8)     = make_float2(acc[mi][ni][0], acc[mi][ni][1]);
      *(float2*)(C + (size_t)(r0+8)*Nc + c0 + ni*8) = make_float2(acc[mi][ni][2], acc[mi][ni][3]);
    }
  }
}

// ================= fused projection + uv =================
#define PPADH 72
#define PA_TILE (64*PPADH)
#define PB_TILE (128*PPADH)
#define PSTAGE (2*PA_TILE + PB_TILE)
#define PROJ_SMEM (2*PSTAGE*2)

__device__ __forceinline__ void stage_load_proj(
    __half* s, const __half* Ah, const __half* Al, const __half* Bh,
    int bm, int K, int k0, int tid)
{
  #pragma unroll
  for (int q=0;q<2;q++){
    int chunk = tid + q*256;
    int row = chunk>>3, cc = chunk&7;
    uint32_t so = sptr(s + row*PPADH + cc*8);
    cp16(so, Ah + (size_t)(bm+row)*K + k0 + cc*8);
    uint32_t so2 = sptr(s + PA_TILE + row*PPADH + cc*8);
    cp16(so2, Al + (size_t)(bm+row)*K + k0 + cc*8);
  }
  #pragma unroll
  for (int q=0;q<4;q++){
    int chunk = tid + q*256;
    int row = chunk>>3, cc = chunk&7;
    uint32_t so = sptr(s + 2*PA_TILE + row*PPADH + cc*8);
    cp16(so, Bh + (size_t)row*K + k0 + cc*8);
  }
}

__global__ void __launch_bounds__(256)
proj_uv(const __half* __restrict__ Ah, const __half* __restrict__ Al,
        const __half* __restrict__ Bh)
{
  extern __shared__ __half smh[];
  __shared__ float ssum[4][64];
  __shared__ float sscale[64];
  const int tid = threadIdx.x;
  const int wid = tid>>5, lane = tid&31;
  const int bm = blockIdx.y*64;
  const int wm = (wid&1)*32;
  const int wn = (wid>>1)*32;
  const int K = D_;
  const int KT = K>>6;

  float acc[2][4][4];
  #pragma unroll
  for (int i=0;i<2;i++)
    #pragma unroll
    for (int j=0;j<4;j++)
      #pragma unroll
      for (int q=0;q<4;q++) acc[i][j][q]=0.f;

  stage_load_proj(smh, Ah, Al, Bh, bm, K, 0, tid);
  CP_COMMIT();

  const int arow = lane & 15;
  const int acol8 = (lane>>4)*8;
  const int brow = (lane&7) + ((lane>>4)<<3);
  const int bsel = ((lane>>3)&1)*8;

  for (int c=0; c<KT; c++){
    if (c+1 < KT){
      stage_load_proj(smh + ((c+1)&1)*PSTAGE, Ah, Al, Bh, bm, K, (c+1)*64, tid);
      CP_COMMIT();
      CP_WAIT(1);
    } else {
      CP_WAIT(0);
    }
    __syncthreads();

    __half* s = smh + (c&1)*PSTAGE;
    const uint32_t sAh = sptr(s);
    const uint32_t sAl = sAh + PA_TILE*2;
    const uint32_t sBh = sAh + 2*PA_TILE*2;

    #pragma unroll
    for (int ks=0; ks<4; ks++){
      uint32_t ah[2][4], al[2][4], bh[2][4];
      #pragma unroll
      for (int mi=0; mi<2; mi++){
        uint32_t off = (uint32_t)((wm + mi*16 + arow)*PPADH + ks*16 + acol8)*2;
        ldsm4(ah[mi], sAh + off);
        ldsm4(al[mi], sAl + off);
      }
      #pragma unroll
      for (int p=0; p<2; p++){
        uint32_t off = (uint32_t)((wn + p*16 + brow)*PPADH + ks*16 + bsel)*2;
        ldsm4(bh[p], sBh + off);
      }
      #pragma unroll
      for (int mi=0; mi<2; mi++)
        #pragma unroll
        for (int p=0; p<2; p++)
          #pragma unroll
          for (int h=0; h<2; h++){
            const int ni = p*2 + h;
            mma_h(acc[mi][ni], ah[mi], &bh[p][h*2]);
            mma_h(acc[mi][ni], al[mi], &bh[p][h*2]);
          }
    }
    __syncthreads();
  }

  const int colblk = wid>>1;
  #pragma unroll
  for (int mi=0; mi<2; mi++){
    #pragma unroll
    for (int qh=0; qh<2; qh++){
      float sv = 0.f;
      #pragma unroll
      for (int ni=0; ni<4; ni++)
        sv += fabsf(acc[mi][ni][qh*2]) + fabsf(acc[mi][ni][qh*2+1]);
      sv += __shfl_xor_sync(0xffffffffu, sv, 1);
      sv += __shfl_xor_sync(0xffffffffu, sv, 2);
      if ((lane&3)==0)
        ssum[colblk][wm + mi*16 + qh*8 + (lane>>2)] = sv;
    }
  }
  __syncthreads();
  if (tid < 64){
    float str = ssum[0][tid] + ssum[1][tid];
    float sct = ssum[2][tid] + ssum[3][tid];
    sscale[tid] = __fdividef(1.f, 1e-8f + str*sct);
  }
  __syncthreads();
  #pragma unroll
  for (int mi=0; mi<2; mi++){
    #pragma unroll
    for (int ni=0; ni<4; ni++){
      #pragma unroll
      for (int q=0; q<4; q++){
        int rloc = wm + mi*16 + (q>>1)*8 + (lane>>2);
        int t = bm + rloc;
        int col = wn + (lane&3)*2 + ni*8 + (q&1);
        float vabs = fabsf(acc[mi][ni][q]);
        if (col < 64) g_u[t*TR_ + col] = vabs;
        else          g_v[t*CC_ + col - 64] = vabs * sscale[rloc];
      }
    }
  }
}

// ---------------- scan ----------------
__device__ __forceinline__ void make_decay(float ai, float bj, float& dre, float& dim){
  double rho = exp(-(double)fabsf(ai));
  double sb, cb; sincos((double)bj, &sb, &cb);
  dre = (float)(rho*cb); dim = (float)(rho*sb);
}

__global__ void scan_passA(const unsigned* __restrict__ start,
                           const float* __restrict__ a, const float* __restrict__ b,
                           int layer){
  const int i = blockIdx.y;
  const int c = blockIdx.x;
  const int j = threadIdx.x;
  const float ai = a[layer*TR_ + i];
  const float bj = b[layer*CC_ + j];
  float dre, dim;
  make_decay(ai, bj, dre, dim);
  float sre=0.f, sim=0.f;
  int reset = 0;
  const int t0 = c*CHUNK_;
  for (int t=t0; t<t0+CHUNK_; t++){
    if (start[t]){ sre=0.f; sim=0.f; reset=1; }
    float p = g_u[t*TR_+i]*g_v[t*CC_+j];
    float nre = fmaf(sre,dre, fmaf(-sim,dim,p));
    float nim = fmaf(sre,dim, sim*dre);
    sre=nre; sim=nim;
  }
  const int ch = i*CC_+j;
  g_Bend[c*NCH_+ch]=make_float2(sre,sim);
  float2 A;
  if (reset){ A=make_float2(0.f,0.f); }
  else {
    double rhoL = exp(-(double)fabsf(ai)*(double)CHUNK_);
    double sL,cL; sincos((double)bj*(double)CHUNK_, &sL,&cL);
    A = make_float2((float)(rhoL*cL), (float)(rhoL*sL));
  }
  g_Amat[c*NCH_+ch]=A;
}

__global__ void scan_passB(const float* __restrict__ state, int layer){
  int ch = blockIdx.x*blockDim.x + threadIdx.x;
  float sre = state[layer*NCH_ + ch];
  float sim = 0.f;
  #pragma unroll
  for (int c=0;c<NCHUNK_;c++){
    g_sinit[c*NCH_+ch] = make_float2(sre,sim);
    float2 A = g_Amat[c*NCH_+ch];
    float2 B = g_Bend[c*NCH_+ch];
    float nre = A.x*sre - A.y*sim + B.x;
    float nim = A.x*sim + A.y*sre + B.y;
    sre=nre; sim=nim;
  }
}

// full scan + feature emission (single fp16)
__global__ void scan_passC(const unsigned* __restrict__ start,
                           const float* __restrict__ a, const float* __restrict__ b,
                           int layer){
  const int i = blockIdx.y, c = blockIdx.x, j = threadIdx.x;
  float dre, dim;
  make_decay(a[layer*TR_+i], b[layer*CC_+j], dre, dim);
  const int ch = i*CC_+j;
  float2 s0 = g_sinit[c*NCH_+ch];
  float sre=s0.x, sim=s0.y;
  const int t0=c*CHUNK_;
  for (int t=t0;t<t0+CHUNK_;t++){
    if (start[t]){ sre=0.f; sim=0.f; }
    float p = g_u[t*TR_+i]*g_v[t*CC_+j];
    float nre = fmaf(sre,dre, fmaf(-sim,dim,p));
    float nim = fmaf(sre,dim, sim*dre);
    sre=nre; sim=nim;
    float r2 = fmaf(sre,sre, sim*sim);
    float f;
    if (r2 > 1e-24f){
      float rr = sqrtf(r2);
      f = __fdividef(log1pf(rr), rr);
    } else {
      f = 1.f;
    }
    size_t o0 = (size_t)t*F_ + ch;
    g_sclh[o0]        = __float2half_rn(f*sim);
    g_sclh[o0 + NCH_] = __float2half_rn(f*sre);
  }
}

// ================= LayerNorm + leaky ReLU =================
__device__ __forceinline__ void reduce2(float &s, float &ss){
  __shared__ float sh[8], sh2[8];
  int lane = threadIdx.x & 31, w = threadIdx.x >> 5;
  #pragma unroll
  for (int o=16;o>0;o>>=1){
    s  += __shfl_down_sync(0xffffffffu, s,  o);
    ss += __shfl_down_sync(0xffffffffu, ss, o);
  }
  if (lane==0){ sh[w]=s; sh2[w]=ss; }
  __syncthreads();
  if (w==0){
    s  = (lane<8)? sh[lane]  : 0.f;
    ss = (lane<8)? sh2[lane] : 0.f;
    #pragma unroll
    for (int o=4;o>0;o>>=1){
      s  += __shfl_down_sync(0xffffffffu, s,  o);
      ss += __shfl_down_sync(0xffffffffu, ss, o);
    }
    if (lane==0){ sh[0]=s; sh2[0]=ss; }
  }
  __syncthreads();
  s = sh[0]; ss = sh2[0];
}

__global__ void ln_leaky(const float* __restrict__ zin, const float* __restrict__ bias,
                         const float* __restrict__ gamma, const float* __restrict__ beta,
                         float* __restrict__ zout, float* __restrict__ xacc,
                         __half* __restrict__ zh, __half* __restrict__ zl,
                         __half* __restrict__ xh, __half* __restrict__ xl){
  const int t = blockIdx.x;
  const int tid = threadIdx.x;
  float v0 = zin[t*D_ + tid]       + bias[tid];
  float v1 = zin[t*D_ + 256 + tid] + bias[256+tid];
  float s = v0+v1;
  float ss = v0*v0 + v1*v1;
  reduce2(s, ss);
  float m = s * (1.f/512.f);
  float var = ss * (1.f/512.f) - m*m;
  float rinv = rsqrtf(var + 1e-5f);
  float y0 = (v0 - m)*rinv*gamma[tid]     + beta[tid];
  float y1 = (v1 - m)*rinv*gamma[256+tid] + beta[256+tid];
  y0 = (y0 > 0.f) ? y0 : 0.01f*y0;
  y1 = (y1 > 0.f) ? y1 : 0.01f*y1;
  if (zout){
    zout[t*D_ + tid]       = y0;
    zout[t*D_ + 256 + tid] = y1;
  }
  if (xacc){
    float x0 = xacc[t*D_ + tid]       + y0;
    float x1 = xacc[t*D_ + 256 + tid] + y1;
    xacc[t*D_ + tid]       = x0;
    xacc[t*D_ + 256 + tid] = x1;
    if (xh){
      emit2(x0, xh + t*D_ + tid,       xl + t*D_ + tid);
      emit2(x1, xh + t*D_ + 256 + tid, xl + t*D_ + 256 + tid);
    }
  }
  if (zh){
    emit2(y0, zh + t*D_ + tid,       zl + t*D_ + tid);
    emit2(y1, zh + t*D_ + 256 + tid, zl + t*D_ + 256 + tid);
  }
}

// ================= launcher =================
extern "C" void kernel_launch(void* const* d_in, const int* in_sizes, int n_in,
                              void* d_out, int out_size) {
  const float*    x     = (const float*)d_in[0];
  const float*    state = (const float*)d_in[1];
  const unsigned* start = (const unsigned*)d_in[2];
  const float*    Wtr   = (const float*)d_in[3];
  const float*    Wc    = (const float*)d_in[4];
  const float*    a     = (const float*)d_in[5];
  const float*    b     = (const float*)d_in[6];
  const float*    W0    = (const float*)d_in[7];
  const float*    b0    = (const float*)d_in[8];
  const float*    g0    = (const float*)d_in[9];
  const float*    beta0 = (const float*)d_in[10];
  const float*    W1    = (const float*)d_in[11];
  const float*    b1    = (const float*)d_in[12];
  const float*    g1    = (const float*)d_in[13];
  const float*    beta1 = (const float*)d_in[14];
  float* out = (float*)d_out;

  float *px, *ph, *pzt;
  __half *psh, *pw0h, *pw1h, *pwph, *pz0h, *pz0l, *pxh, *pxl;
  cudaGetSymbolAddress((void**)&px,    g_x);
  cudaGetSymbolAddress((void**)&ph,    g_h);
  cudaGetSymbolAddress((void**)&pzt,   g_ztmp);
  cudaGetSymbolAddress((void**)&psh,   g_sclh);
  cudaGetSymbolAddress((void**)&pw0h,  g_w0h);
  cudaGetSymbolAddress((void**)&pw1h,  g_w1h);
  cudaGetSymbolAddress((void**)&pwph,  g_wph);
  cudaGetSymbolAddress((void**)&pz0h,  g_z0h);
  cudaGetSymbolAddress((void**)&pz0l,  g_z0l);
  cudaGetSymbolAddress((void**)&pxh,   g_xh);
  cudaGetSymbolAddress((void**)&pxl,   g_xl);

  cudaFuncSetAttribute(gemm1,   cudaFuncAttributeMaxDynamicSharedMemorySize, GEMM1_SMEM);
  cudaFuncSetAttribute(gemm2,   cudaFuncAttributeMaxDynamicSharedMemorySize, GEMM_SMEM);
  cudaFuncSetAttribute(proj_uv, cudaFuncAttributeMaxDynamicSharedMemorySize, PROJ_SMEM);

  copy_split_x<<<(T_*D_)/256, 256>>>(x);
  cvt_h<<<(L_*D_*F_ + 255)/256, 256>>>(W0, pw0h, L_*D_*F_);
  cvt_h<<<(L_*D_*D_ + 255)/256, 256>>>(W1, pw1h, L_*D_*D_);
  prep_wproj<<<(L_*128*D_ + 255)/256, 256>>>(Wtr, Wc);

  for (int l=0; l<L_; l++){
    proj_uv<<<dim3(1, T_/64), 256, PROJ_SMEM>>>(pxh, pxl, pwph + (size_t)l*128*D_);

    scan_passA<<<dim3(NCHUNK_, TR_), CC_>>>(start, a, b, l);
    scan_passB<<<NCH_/256, 256>>>(state, l);
    scan_passC<<<dim3(NCHUNK_, TR_), CC_>>>(start, a, b, l);

    // h = scaled @ W0^T   (M=4096, N=512, K=8192), 1-term fp16
    gemm1<<<dim3(D_/128, T_/128), 256, GEMM1_SMEM>>>(
        psh, pw0h + (size_t)l*D_*F_, ph, F_, D_);
    ln_leaky<<<T_, 256>>>(ph, b0 + l*D_, g0 + l*D_, beta0 + l*D_,
                          nullptr, nullptr, pz0h, pz0l, nullptr, nullptr);

    // h = z0 @ W1^T   (M=4096, N=512, K=512), 2-term
    gemm2<<<dim3(D_/128, T_/128), 256, GEMM_SMEM>>>(
        pz0h, pz0l, pw1h + (size_t)l*D_*D_, ph, D_, D_);
    float* zo = (l == L_-1) ? out : pzt;
    bool last = (l == L_-1);
    ln_leaky<<<T_, 256>>>(ph, b1 + l*D_, g1 + l*D_, beta1 + l*D_,
                          zo, px, nullptr, nullptr,
                          last ? nullptr : pxh, last ? nullptr : pxl);
  }
}

// round 9
// speedup vs baseline: 2.2392x; 1.0245x over previous
#include <cuda_runtime.h>
#include <cuda_fp16.h>
#include <math.h>
#include <stdint.h>

#define T_ 4096
#define D_ 512
#define TR_ 64
#define CC_ 64
#define L_ 3
#define F_ 8192
#define NCH_ 4096
#define NCHUNK_ 16
#define CHUNK_ 256

// ---------------- scratch ----------------
__device__ float g_x[T_*D_];
__device__ float g_u[T_*TR_];
__device__ float g_v[T_*CC_];
__device__ float2 g_Bend[NCHUNK_*NCH_];
__device__ float2 g_Amat[NCHUNK_*NCH_];
__device__ float g_h[T_*D_];
__device__ float g_ztmp[T_*D_];
__device__ __half g_sclh[(size_t)T_*F_];
__device__ __half g_w0h[L_*D_*F_];
__device__ __half g_w1h[L_*D_*D_];
__device__ __half g_wph[L_*128*D_];
__device__ __half g_z0h[T_*D_];
__device__ __half g_xh[T_*D_];

// ---------------- low-level helpers (baseline PTX @ compute_103) ----------------
__device__ __forceinline__ uint32_t sptr(const void* p){
  return (uint32_t)__cvta_generic_to_shared(p);
}
__device__ __forceinline__ void cp16(uint32_t s, const void* g){
  asm volatile("cp.async.cg.shared.global [%0], [%1], 16;" :: "r"(s), "l"(g));
}
#define CP_COMMIT() asm volatile("cp.async.commit_group;" ::: "memory")
#define CP_WAIT(n)  asm volatile("cp.async.wait_group %0;" :: "n"(n) : "memory")

__device__ __forceinline__ void ldsm4(uint32_t* r, uint32_t a){
  asm volatile("ldmatrix.sync.aligned.m8n8.x4.shared.b16 {%0,%1,%2,%3}, [%4];"
    : "=r"(r[0]),"=r"(r[1]),"=r"(r[2]),"=r"(r[3]) : "r"(a));
}
__device__ __forceinline__ void mma_h(float* d, const uint32_t* a, const uint32_t* b){
  asm volatile("mma.sync.aligned.m16n8k16.row.col.f32.f16.f16.f32 "
    "{%0,%1,%2,%3}, {%4,%5,%6,%7}, {%8,%9}, {%0,%1,%2,%3};"
    : "+f"(d[0]),"+f"(d[1]),"+f"(d[2]),"+f"(d[3])
    : "r"(a[0]),"r"(a[1]),"r"(a[2]),"r"(a[3]), "r"(b[0]),"r"(b[1]));
}

// ---------------- prep kernels ----------------
__global__ void cvt_h(const float* __restrict__ src, __half* __restrict__ dst, int n){
  int i = blockIdx.x*blockDim.x + threadIdx.x;
  if (i < n) dst[i] = __float2half_rn(src[i]);
}

__global__ void copy_split_x(const float* __restrict__ src){
  int i = blockIdx.x*blockDim.x + threadIdx.x;
  float v = src[i];
  g_x[i] = v;
  g_xh[i] = __float2half_rn(v);
}

__global__ void prep_wproj(const float* __restrict__ Wtr, const float* __restrict__ Wc){
  int idx = blockIdx.x*blockDim.x + threadIdx.x;
  if (idx >= L_*128*D_) return;
  int l = idx / (128*D_);
  int rem = idx % (128*D_);
  int row = rem / D_, k = rem % D_;
  float v = (row < 64) ? Wtr[((size_t)l*64+row)*D_+k] : Wc[((size_t)l*64+row-64)*D_+k];
  g_wph[idx] = __float2half_rn(v);
}

// ================= 1-term fp16 GEMM: C = Ah @ Bh^T =================
// BM=BN=128, BK=128, 3-stage, 256 thr (8 warps 4x2), warp tile 32x64.
#define PAD1 136                        // halves per row (128 data + 8 pad)
#define TILE1 (128*PAD1)
#define STAGE1 (2*TILE1)                // Ah, Bh
#define GEMM1_SMEM (3*STAGE1*2)         // 208896 B

__device__ __forceinline__ void stage_load1(
    __half* s, const __half* Ah, const __half* Bh,
    int bm, int bn, int K, int k0, int tid)
{
  const __half* src[2] = {Ah, Bh};
  #pragma unroll
  for (int t=0;t<2;t++){
    int rb = (t==0)? bm : bn;
    #pragma unroll
    for (int q=0;q<8;q++){
      int chunk = tid + q*256;           // 2048 16B-chunks per tensor
      int row = chunk>>4, cc = chunk&15;
      uint32_t so = sptr(s + t*TILE1 + row*PAD1 + cc*8);
      cp16(so, src[t] + (size_t)(rb+row)*K + k0 + cc*8);
    }
  }
}

__global__ void __launch_bounds__(256)
gemm1(const __half* __restrict__ Ah, const __half* __restrict__ Bh,
      float* __restrict__ C, int K, int Nc)
{
  extern __shared__ __half smh[];
  const int tid = threadIdx.x;
  const int wid = tid>>5, lane = tid&31;
  const int bm = blockIdx.y*128, bn = blockIdx.x*128;
  const int wm = (wid>>1)*32;
  const int wn = (wid&1)*64;
  const int KT = K>>7;                  // chunks of 128

  float acc[2][8][4];
  #pragma unroll
  for (int i=0;i<2;i++)
    #pragma unroll
    for (int j=0;j<8;j++)
      #pragma unroll
      for (int q=0;q<4;q++) acc[i][j][q]=0.f;

  stage_load1(smh, Ah, Bh, bm, bn, K, 0, tid);
  CP_COMMIT();
  if (KT > 1){
    stage_load1(smh + STAGE1, Ah, Bh, bm, bn, K, 128, tid);
    CP_COMMIT();
  }

  const int arow = lane & 15;
  const int acol8 = (lane>>4)*8;
  const int brow = (lane&7) + ((lane>>4)<<3);
  const int bsel = ((lane>>3)&1)*8;

  int bufc = 0;
  for (int c=0; c<KT; c++){
    if (c+1 < KT) { CP_WAIT(1); } else { CP_WAIT(0); }
    __syncthreads();

    __half* s = smh + bufc*STAGE1;
    const uint32_t sAh = sptr(s);
    const uint32_t sBh = sAh + TILE1*2;

    #pragma unroll
    for (int ks=0; ks<8; ks++){
      uint32_t ah[2][4], bh[4][4];
      #pragma unroll
      for (int mi=0; mi<2; mi++){
        uint32_t off = (uint32_t)((wm + mi*16 + arow)*PAD1 + ks*16 + acol8)*2;
        ldsm4(ah[mi], sAh + off);
      }
      #pragma unroll
      for (int p=0; p<4; p++){
        uint32_t off = (uint32_t)((wn + p*16 + brow)*PAD1 + ks*16 + bsel)*2;
        ldsm4(bh[p], sBh + off);
      }
      #pragma unroll
      for (int mi=0; mi<2; mi++)
        #pragma unroll
        for (int p=0; p<4; p++)
          #pragma unroll
          for (int h=0; h<2; h++)
            mma_h(acc[mi][p*2+h], ah[mi], &bh[p][h*2]);
    }

    if (c+2 < KT){
      int buf2 = bufc + 2; if (buf2 >= 3) buf2 -= 3;
      stage_load1(smh + buf2*STAGE1, Ah, Bh, bm, bn, K, (c+2)*128, tid);
      CP_COMMIT();
    }
    bufc++; if (bufc == 3) bufc = 0;
  }

  #pragma unroll
  for (int mi=0; mi<2; mi++){
    const int r0 = bm + wm + mi*16 + (lane>>2);
    const int c0 = bn + wn + (lane&3)*2;
    #pragma unroll
    for (int ni=0; ni<8; ni++){
      *(float2*)(C + (size_t)r0*Nc + c0 + ni*8)     = make_float2(acc[mi][ni][0], acc[mi][ni][1]);
      *(float2*)(C + (size_t)(r0+8)*Nc + c0 + ni*8) = make_float2(acc[mi][ni][2], acc[mi][ni][3]);
    }
  }
}

// ================= fused projection + uv (1-term) =================
#define PPADH 72
#define PA_TILE (64*PPADH)
#define PB_TILE (128*PPADH)
#define PSTAGE (PA_TILE + PB_TILE)
#define PROJ_SMEM (2*PSTAGE*2)

__device__ __forceinline__ void stage_load_proj(
    __half* s, const __half* Ah, const __half* Bh,
    int bm, int K, int k0, int tid)
{
  #pragma unroll
  for (int q=0;q<2;q++){
    int chunk = tid + q*256;
    int row = chunk>>3, cc = chunk&7;
    uint32_t so = sptr(s + row*PPADH + cc*8);
    cp16(so, Ah + (size_t)(bm+row)*K + k0 + cc*8);
  }
  #pragma unroll
  for (int q=0;q<4;q++){
    int chunk = tid + q*256;
    int row = chunk>>3, cc = chunk&7;
    uint32_t so = sptr(s + PA_TILE + row*PPADH + cc*8);
    cp16(so, Bh + (size_t)row*K + k0 + cc*8);
  }
}

__global__ void __launch_bounds__(256)
proj_uv(const __half* __restrict__ Ah, const __half* __restrict__ Bh)
{
  extern __shared__ __half smh[];
  __shared__ float ssum[4][64];
  __shared__ float sscale[64];
  const int tid = threadIdx.x;
  const int wid = tid>>5, lane = tid&31;
  const int bm = blockIdx.y*64;
  const int wm = (wid&1)*32;
  const int wn = (wid>>1)*32;
  const int K = D_;
  const int KT = K>>6;

  float acc[2][4][4];
  #pragma unroll
  for (int i=0;i<2;i++)
    #pragma unroll
    for (int j=0;j<4;j++)
      #pragma unroll
      for (int q=0;q<4;q++) acc[i][j][q]=0.f;

  stage_load_proj(smh, Ah, Bh, bm, K, 0, tid);
  CP_COMMIT();

  const int arow = lane & 15;
  const int acol8 = (lane>>4)*8;
  const int brow = (lane&7) + ((lane>>4)<<3);
  const int bsel = ((lane>>3)&1)*8;

  for (int c=0; c<KT; c++){
    if (c+1 < KT){
      stage_load_proj(smh + ((c+1)&1)*PSTAGE, Ah, Bh, bm, K, (c+1)*64, tid);
      CP_COMMIT();
      CP_WAIT(1);
    } else {
      CP_WAIT(0);
    }
    __syncthreads();

    __half* s = smh + (c&1)*PSTAGE;
    const uint32_t sAh = sptr(s);
    const uint32_t sBh = sAh + PA_TILE*2;

    #pragma unroll
    for (int ks=0; ks<4; ks++){
      uint32_t ah[2][4], bh[2][4];
      #pragma unroll
      for (int mi=0; mi<2; mi++){
        uint32_t off = (uint32_t)((wm + mi*16 + arow)*PPADH + ks*16 + acol8)*2;
        ldsm4(ah[mi], sAh + off);
      }
      #pragma unroll
      for (int p=0; p<2; p++){
        uint32_t off = (uint32_t)((wn + p*16 + brow)*PPADH + ks*16 + bsel)*2;
        ldsm4(bh[p], sBh + off);
      }
      #pragma unroll
      for (int mi=0; mi<2; mi++)
        #pragma unroll
        for (int p=0; p<2; p++)
          #pragma unroll
          for (int h=0; h<2; h++)
            mma_h(acc[mi][p*2+h], ah[mi], &bh[p][h*2]);
    }
    __syncthreads();
  }

  const int colblk = wid>>1;
  #pragma unroll
  for (int mi=0; mi<2; mi++){
    #pragma unroll
    for (int qh=0; qh<2; qh++){
      float sv = 0.f;
      #pragma unroll
      for (int ni=0; ni<4; ni++)
        sv += fabsf(acc[mi][ni][qh*2]) + fabsf(acc[mi][ni][qh*2+1]);
      sv += __shfl_xor_sync(0xffffffffu, sv, 1);
      sv += __shfl_xor_sync(0xffffffffu, sv, 2);
      if ((lane&3)==0)
        ssum[colblk][wm + mi*16 + qh*8 + (lane>>2)] = sv;
    }
  }
  __syncthreads();
  if (tid < 64){
    float str = ssum[0][tid] + ssum[1][tid];
    float sct = ssum[2][tid] + ssum[3][tid];
    sscale[tid] = __fdividef(1.f, 1e-8f + str*sct);
  }
  __syncthreads();
  #pragma unroll
  for (int mi=0; mi<2; mi++){
    #pragma unroll
    for (int ni=0; ni<4; ni++){
      #pragma unroll
      for (int q=0; q<4; q++){
        int rloc = wm + mi*16 + (q>>1)*8 + (lane>>2);
        int t = bm + rloc;
        int col = wn + (lane&3)*2 + ni*8 + (q&1);
        float vabs = fabsf(acc[mi][ni][q]);
        if (col < 64) g_u[t*TR_ + col] = vabs;
        else          g_v[t*CC_ + col - 64] = vabs * sscale[rloc];
      }
    }
  }
}

// ---------------- scan ----------------
__device__ __forceinline__ void make_decay(float ai, float bj, float& dre, float& dim){
  double rho = exp(-(double)fabsf(ai));
  double sb, cb; sincos((double)bj, &sb, &cb);
  dre = (float)(rho*cb); dim = (float)(rho*sb);
}

__global__ void scan_passA(const unsigned* __restrict__ start,
                           const float* __restrict__ a, const float* __restrict__ b,
                           int layer){
  const int i = blockIdx.y;
  const int c = blockIdx.x;
  const int j = threadIdx.x;
  const float ai = a[layer*TR_ + i];
  const float bj = b[layer*CC_ + j];
  float dre, dim;
  make_decay(ai, bj, dre, dim);
  float sre=0.f, sim=0.f;
  int reset = 0;
  const int t0 = c*CHUNK_;
  for (int t=t0; t<t0+CHUNK_; t++){
    if (start[t]){ sre=0.f; sim=0.f; reset=1; }
    float p = g_u[t*TR_+i]*g_v[t*CC_+j];
    float nre = fmaf(sre,dre, fmaf(-sim,dim,p));
    float nim = fmaf(sre,dim, sim*dre);
    sre=nre; sim=nim;
  }
  const int ch = i*CC_+j;
  g_Bend[c*NCH_+ch]=make_float2(sre,sim);
  float2 A;
  if (reset){ A=make_float2(0.f,0.f); }
  else {
    double rhoL = exp(-(double)fabsf(ai)*(double)CHUNK_);
    double sL,cL; sincos((double)bj*(double)CHUNK_, &sL,&cL);
    A = make_float2((float)(rhoL*cL), (float)(rhoL*sL));
  }
  g_Amat[c*NCH_+ch]=A;
}

// pass C with folded chunk-combine (ex-passB): per-block redundant s_init
__global__ void scan_passC(const unsigned* __restrict__ start,
                           const float* __restrict__ a, const float* __restrict__ b,
                           const float* __restrict__ state, int layer){
  const int i = blockIdx.y, c = blockIdx.x, j = threadIdx.x;
  float dre, dim;
  make_decay(a[layer*TR_+i], b[layer*CC_+j], dre, dim);
  const int ch = i*CC_+j;
  // fold passB: combine chunks 0..c-1 starting from state
  float sre = state[layer*NCH_ + ch];
  float sim = 0.f;
  for (int cc=0; cc<c; cc++){
    float2 A = g_Amat[cc*NCH_+ch];
    float2 B = g_Bend[cc*NCH_+ch];
    float nr = A.x*sre - A.y*sim + B.x;
    float ni = A.x*sim + A.y*sre + B.y;
    sre=nr; sim=ni;
  }
  const int t0=c*CHUNK_;
  for (int t=t0;t<t0+CHUNK_;t++){
    if (start[t]){ sre=0.f; sim=0.f; }
    float p = g_u[t*TR_+i]*g_v[t*CC_+j];
    float nre = fmaf(sre,dre, fmaf(-sim,dim,p));
    float nim = fmaf(sre,dim, sim*dre);
    sre=nre; sim=nim;
    float r2 = fmaf(sre,sre, sim*sim);
    float f;
    if (r2 > 1e-24f){
      float rr = sqrtf(r2);
      f = __fdividef(log1pf(rr), rr);
    } else {
      f = 1.f;
    }
    size_t o0 = (size_t)t*F_ + ch;
    g_sclh[o0]        = __float2half_rn(f*sim);
    g_sclh[o0 + NCH_] = __float2half_rn(f*sre);
  }
}

// ================= LayerNorm + leaky ReLU =================
__device__ __forceinline__ void reduce2(float &s, float &ss){
  __shared__ float sh[8], sh2[8];
  int lane = threadIdx.x & 31, w = threadIdx.x >> 5;
  #pragma unroll
  for (int o=16;o>0;o>>=1){
    s  += __shfl_down_sync(0xffffffffu, s,  o);
    ss += __shfl_down_sync(0xffffffffu, ss, o);
  }
  if (lane==0){ sh[w]=s; sh2[w]=ss; }
  __syncthreads();
  if (w==0){
    s  = (lane<8)? sh[lane]  : 0.f;
    ss = (lane<8)? sh2[lane] : 0.f;
    #pragma unroll
    for (int o=4;o>0;o>>=1){
      s  += __shfl_down_sync(0xffffffffu, s,  o);
      ss += __shfl_down_sync(0xffffffffu, ss, o);
    }
    if (lane==0){ sh[0]=s; sh2[0]=ss; }
  }
  __syncthreads();
  s = sh[0]; ss = sh2[0];
}

__global__ void ln_leaky(const float* __restrict__ zin, const float* __restrict__ bias,
                         const float* __restrict__ gamma, const float* __restrict__ beta,
                         float* __restrict__ zout, float* __restrict__ xacc,
                         __half* __restrict__ zh, __half* __restrict__ xh){
  const int t = blockIdx.x;
  const int tid = threadIdx.x;
  float v0 = zin[t*D_ + tid]       + bias[tid];
  float v1 = zin[t*D_ + 256 + tid] + bias[256+tid];
  float s = v0+v1;
  float ss = v0*v0 + v1*v1;
  reduce2(s, ss);
  float m = s * (1.f/512.f);
  float var = ss * (1.f/512.f) - m*m;
  float rinv = rsqrtf(var + 1e-5f);
  float y0 = (v0 - m)*rinv*gamma[tid]     + beta[tid];
  float y1 = (v1 - m)*rinv*gamma[256+tid] + beta[256+tid];
  y0 = (y0 > 0.f) ? y0 : 0.01f*y0;
  y1 = (y1 > 0.f) ? y1 : 0.01f*y1;
  if (zout){
    zout[t*D_ + tid]       = y0;
    zout[t*D_ + 256 + tid] = y1;
  }
  if (xacc){
    float x0 = xacc[t*D_ + tid]       + y0;
    float x1 = xacc[t*D_ + 256 + tid] + y1;
    xacc[t*D_ + tid]       = x0;
    xacc[t*D_ + 256 + tid] = x1;
    if (xh){
      xh[t*D_ + tid]       = __float2half_rn(x0);
      xh[t*D_ + 256 + tid] = __float2half_rn(x1);
    }
  }
  if (zh){
    zh[t*D_ + tid]       = __float2half_rn(y0);
    zh[t*D_ + 256 + tid] = __float2half_rn(y1);
  }
}

// ================= launcher =================
extern "C" void kernel_launch(void* const* d_in, const int* in_sizes, int n_in,
                              void* d_out, int out_size) {
  const float*    x     = (const float*)d_in[0];
  const float*    state = (const float*)d_in[1];
  const unsigned* start = (const unsigned*)d_in[2];
  const float*    Wtr   = (const float*)d_in[3];
  const float*    Wc    = (const float*)d_in[4];
  const float*    a     = (const float*)d_in[5];
  const float*    b     = (const float*)d_in[6];
  const float*    W0    = (const float*)d_in[7];
  const float*    b0    = (const float*)d_in[8];
  const float*    g0    = (const float*)d_in[9];
  const float*    beta0 = (const float*)d_in[10];
  const float*    W1    = (const float*)d_in[11];
  const float*    b1    = (const float*)d_in[12];
  const float*    g1    = (const float*)d_in[13];
  const float*    beta1 = (const float*)d_in[14];
  float* out = (float*)d_out;

  float *px, *ph, *pzt;
  __half *psh, *pw0h, *pw1h, *pwph, *pz0h, *pxh;
  cudaGetSymbolAddress((void**)&px,    g_x);
  cudaGetSymbolAddress((void**)&ph,    g_h);
  cudaGetSymbolAddress((void**)&pzt,   g_ztmp);
  cudaGetSymbolAddress((void**)&psh,   g_sclh);
  cudaGetSymbolAddress((void**)&pw0h,  g_w0h);
  cudaGetSymbolAddress((void**)&pw1h,  g_w1h);
  cudaGetSymbolAddress((void**)&pwph,  g_wph);
  cudaGetSymbolAddress((void**)&pz0h,  g_z0h);
  cudaGetSymbolAddress((void**)&pxh,   g_xh);

  cudaFuncSetAttribute(gemm1,   cudaFuncAttributeMaxDynamicSharedMemorySize, GEMM1_SMEM);
  cudaFuncSetAttribute(proj_uv, cudaFuncAttributeMaxDynamicSharedMemorySize, PROJ_SMEM);

  copy_split_x<<<(T_*D_)/256, 256>>>(x);
  cvt_h<<<(L_*D_*F_ + 255)/256, 256>>>(W0, pw0h, L_*D_*F_);
  cvt_h<<<(L_*D_*D_ + 255)/256, 256>>>(W1, pw1h, L_*D_*D_);
  prep_wproj<<<(L_*128*D_ + 255)/256, 256>>>(Wtr, Wc);

  for (int l=0; l<L_; l++){
    // fused projection + uv (1-term)
    proj_uv<<<dim3(1, T_/64), 256, PROJ_SMEM>>>(pxh, pwph + (size_t)l*128*D_);

    scan_passA<<<dim3(NCHUNK_, TR_), CC_>>>(start, a, b, l);
    scan_passC<<<dim3(NCHUNK_, TR_), CC_>>>(start, a, b, state, l);

    // h = scaled @ W0^T   (M=4096, N=512, K=8192), 1-term BK=128
    gemm1<<<dim3(D_/128, T_/128), 256, GEMM1_SMEM>>>(
        psh, pw0h + (size_t)l*D_*F_, ph, F_, D_);
    ln_leaky<<<T_, 256>>>(ph, b0 + l*D_, g0 + l*D_, beta0 + l*D_,
                          nullptr, nullptr, pz0h, nullptr);

    // h = z0 @ W1^T   (M=4096, N=512, K=512), 1-term BK=128
    gemm1<<<dim3(D_/128, T_/128), 256, GEMM1_SMEM>>>(
        pz0h, pw1h + (size_t)l*D_*D_, ph, D_, D_);
    float* zo = (l == L_-1) ? out : pzt;
    bool last = (l == L_-1);
    ln_leaky<<<T_, 256>>>(ph, b1 + l*D_, g1 + l*D_, beta1 + l*D_,
                          zo, px, nullptr, last ? nullptr : pxh);
  }
}

// round 10
// speedup vs baseline: 2.3605x; 1.0542x over previous
#include <cuda_runtime.h>
#include <cuda_fp16.h>
#include <math.h>
#include <stdint.h>

#define T_ 4096
#define D_ 512
#define TR_ 64
#define CC_ 64
#define L_ 3
#define F_ 8192
#define NCH_ 4096
#define NCHUNK_ 16
#define CHUNK_ 256
#define NSPLIT_ 4

// ---------------- scratch ----------------
__device__ float g_x[T_*D_];
__device__ float g_u[T_*TR_];
__device__ float g_v[T_*CC_];
__device__ float2 g_Bend[NCHUNK_*NCH_];
__device__ float2 g_Amat[NCHUNK_*NCH_];
__device__ float g_hp[NSPLIT_][T_*D_];    // split-K partials
__device__ float g_ztmp[T_*D_];
__device__ __half g_sclh[(size_t)T_*F_];
__device__ __half g_w0h[L_*D_*F_];
__device__ __half g_w1h[L_*D_*D_];
__device__ __half g_wph[L_*128*D_];
__device__ __half g_z0h[T_*D_];
__device__ __half g_xh[T_*D_];

// ---------------- low-level helpers (baseline PTX @ compute_103) ----------------
__device__ __forceinline__ uint32_t sptr(const void* p){
  return (uint32_t)__cvta_generic_to_shared(p);
}
__device__ __forceinline__ void cp16(uint32_t s, const void* g){
  asm volatile("cp.async.cg.shared.global [%0], [%1], 16;" :: "r"(s), "l"(g));
}
#define CP_COMMIT() asm volatile("cp.async.commit_group;" ::: "memory")
#define CP_WAIT(n)  asm volatile("cp.async.wait_group %0;" :: "n"(n) : "memory")

__device__ __forceinline__ void ldsm4(uint32_t* r, uint32_t a){
  asm volatile("ldmatrix.sync.aligned.m8n8.x4.shared.b16 {%0,%1,%2,%3}, [%4];"
    : "=r"(r[0]),"=r"(r[1]),"=r"(r[2]),"=r"(r[3]) : "r"(a));
}
__device__ __forceinline__ void mma_h(float* d, const uint32_t* a, const uint32_t* b){
  asm volatile("mma.sync.aligned.m16n8k16.row.col.f32.f16.f16.f32 "
    "{%0,%1,%2,%3}, {%4,%5,%6,%7}, {%8,%9}, {%0,%1,%2,%3};"
    : "+f"(d[0]),"+f"(d[1]),"+f"(d[2]),"+f"(d[3])
    : "r"(a[0]),"r"(a[1]),"r"(a[2]),"r"(a[3]), "r"(b[0]),"r"(b[1]));
}

// ---------------- merged prep kernel ----------------
// ranges: [0, NW0): W0 -> g_w0h ; [NW0, NW0+NW1): W1 -> g_w1h ;
// then wproj (stacked) ; then x copy+cvt.
#define NW0 (L_*D_*F_)
#define NW1 (L_*D_*D_)
#define NWP (L_*128*D_)
#define NX  (T_*D_)
#define NPREP (NW0+NW1+NWP+NX)

__global__ void prep_all(const float* __restrict__ W0, const float* __restrict__ W1,
                         const float* __restrict__ Wtr, const float* __restrict__ Wc,
                         const float* __restrict__ x){
  int i = blockIdx.x*blockDim.x + threadIdx.x;
  if (i < NW0){
    g_w0h[i] = __float2half_rn(W0[i]);
  } else if (i < NW0+NW1){
    int k = i - NW0;
    g_w1h[k] = __float2half_rn(W1[k]);
  } else if (i < NW0+NW1+NWP){
    int idx = i - NW0 - NW1;
    int l = idx / (128*D_);
    int rem = idx % (128*D_);
    int row = rem / D_, k = rem % D_;
    float v = (row < 64) ? Wtr[((size_t)l*64+row)*D_+k] : Wc[((size_t)l*64+row-64)*D_+k];
    g_wph[idx] = __float2half_rn(v);
  } else if (i < NPREP){
    int k = i - NW0 - NW1 - NWP;
    float v = x[k];
    g_x[k] = v;
    g_xh[k] = __float2half_rn(v);
  }
}

// ================= 1-term fp16 GEMM with split-K =================
// C_part[z][m,n] = sum_{k in split z} Ah[m,k]*Bh[n,k]
// BM=BN=128, BK=64, 3-stage, 256 thr, warp tile 32x64, 2 CTAs/SM target.
#define PADH 72
#define TILEH (128*PADH)
#define STAGE1 (2*TILEH)
#define GEMM1_SMEM (3*STAGE1*2)        // 110592 B

__device__ __forceinline__ void stage_load1(
    __half* s, const __half* Ah, const __half* Bh,
    int bm, int bn, int K, int k0, int tid)
{
  const __half* src[2] = {Ah, Bh};
  #pragma unroll
  for (int t=0;t<2;t++){
    int rb = (t==0)? bm : bn;
    #pragma unroll
    for (int q=0;q<4;q++){
      int chunk = tid + q*256;
      int row = chunk>>3, cc = chunk&7;
      uint32_t so = sptr(s + t*TILEH + row*PADH + cc*8);
      cp16(so, src[t] + (size_t)(rb+row)*K + k0 + cc*8);
    }
  }
}

__global__ void __launch_bounds__(256, 2)
gemm1(const __half* __restrict__ Ah, const __half* __restrict__ Bh,
      float* __restrict__ Cbase, int K, int KS, int Nc)
{
  extern __shared__ __half smh[];
  const int tid = threadIdx.x;
  const int wid = tid>>5, lane = tid&31;
  const int bm = blockIdx.y*128, bn = blockIdx.x*128;
  const int kz = blockIdx.z;
  const int kbase = kz * KS;
  float* C = Cbase + (size_t)kz * T_ * D_;
  const int wm = (wid>>1)*32;
  const int wn = (wid&1)*64;
  const int KT = KS>>6;

  float acc[2][8][4];
  #pragma unroll
  for (int i=0;i<2;i++)
    #pragma unroll
    for (int j=0;j<8;j++)
      #pragma unroll
      for (int q=0;q<4;q++) acc[i][j][q]=0.f;

  stage_load1(smh, Ah, Bh, bm, bn, K, kbase, tid);
  CP_COMMIT();
  if (KT > 1){
    stage_load1(smh + STAGE1, Ah, Bh, bm, bn, K, kbase + 64, tid);
    CP_COMMIT();
  }

  const int arow = lane & 15;
  const int acol8 = (lane>>4)*8;
  const int brow = (lane&7) + ((lane>>4)<<3);
  const int bsel = ((lane>>3)&1)*8;

  int bufc = 0;
  for (int c=0; c<KT; c++){
    if (c+1 < KT) { CP_WAIT(1); } else { CP_WAIT(0); }
    __syncthreads();

    __half* s = smh + bufc*STAGE1;
    const uint32_t sAh = sptr(s);
    const uint32_t sBh = sAh + TILEH*2;

    #pragma unroll
    for (int ks=0; ks<4; ks++){
      uint32_t ah[2][4], bh[4][4];
      #pragma unroll
      for (int mi=0; mi<2; mi++){
        uint32_t off = (uint32_t)((wm + mi*16 + arow)*PADH + ks*16 + acol8)*2;
        ldsm4(ah[mi], sAh + off);
      }
      #pragma unroll
      for (int p=0; p<4; p++){
        uint32_t off = (uint32_t)((wn + p*16 + brow)*PADH + ks*16 + bsel)*2;
        ldsm4(bh[p], sBh + off);
      }
      #pragma unroll
      for (int mi=0; mi<2; mi++)
        #pragma unroll
        for (int p=0; p<4; p++)
          #pragma unroll
          for (int h=0; h<2; h++)
            mma_h(acc[mi][p*2+h], ah[mi], &bh[p][h*2]);
    }

    if (c+2 < KT){
      int buf2 = bufc + 2; if (buf2 >= 3) buf2 -= 3;
      stage_load1(smh + buf2*STAGE1, Ah, Bh, bm, bn, K, kbase + (c+2)*64, tid);
      CP_COMMIT();
    }
    bufc++; if (bufc == 3) bufc = 0;
  }

  #pragma unroll
  for (int mi=0; mi<2; mi++){
    const int r0 = bm + wm + mi*16 + (lane>>2);
    const int c0 = bn + wn + (lane&3)*2;
    #pragma unroll
    for (int ni=0; ni<8; ni++){
      *(float2*)(C + (size_t)r0*Nc + c0 + ni*8)     = make_float2(acc[mi][ni][0], acc[mi][ni][1]);
      *(float2*)(C + (size_t)(r0+8)*Nc + c0 + ni*8) = make_float2(acc[mi][ni][2], acc[mi][ni][3]);
    }
  }
}

// ================= fused projection + uv (1-term) =================
#define PPADH 72
#define PA_TILE (64*PPADH)
#define PB_TILE (128*PPADH)
#define PSTAGE (PA_TILE + PB_TILE)
#define PROJ_SMEM (2*PSTAGE*2)

__device__ __forceinline__ void stage_load_proj(
    __half* s, const __half* Ah, const __half* Bh,
    int bm, int K, int k0, int tid)
{
  #pragma unroll
  for (int q=0;q<2;q++){
    int chunk = tid + q*256;
    int row = chunk>>3, cc = chunk&7;
    uint32_t so = sptr(s + row*PPADH + cc*8);
    cp16(so, Ah + (size_t)(bm+row)*K + k0 + cc*8);
  }
  #pragma unroll
  for (int q=0;q<4;q++){
    int chunk = tid + q*256;
    int row = chunk>>3, cc = chunk&7;
    uint32_t so = sptr(s + PA_TILE + row*PPADH + cc*8);
    cp16(so, Bh + (size_t)row*K + k0 + cc*8);
  }
}

__global__ void __launch_bounds__(256)
proj_uv(const __half* __restrict__ Ah, const __half* __restrict__ Bh)
{
  extern __shared__ __half smh[];
  __shared__ float ssum[4][64];
  __shared__ float sscale[64];
  const int tid = threadIdx.x;
  const int wid = tid>>5, lane = tid&31;
  const int bm = blockIdx.y*64;
  const int wm = (wid&1)*32;
  const int wn = (wid>>1)*32;
  const int K = D_;
  const int KT = K>>6;

  float acc[2][4][4];
  #pragma unroll
  for (int i=0;i<2;i++)
    #pragma unroll
    for (int j=0;j<4;j++)
      #pragma unroll
      for (int q=0;q<4;q++) acc[i][j][q]=0.f;

  stage_load_proj(smh, Ah, Bh, bm, K, 0, tid);
  CP_COMMIT();

  const int arow = lane & 15;
  const int acol8 = (lane>>4)*8;
  const int brow = (lane&7) + ((lane>>4)<<3);
  const int bsel = ((lane>>3)&1)*8;

  for (int c=0; c<KT; c++){
    if (c+1 < KT){
      stage_load_proj(smh + ((c+1)&1)*PSTAGE, Ah, Bh, bm, K, (c+1)*64, tid);
      CP_COMMIT();
      CP_WAIT(1);
    } else {
      CP_WAIT(0);
    }
    __syncthreads();

    __half* s = smh + (c&1)*PSTAGE;
    const uint32_t sAh = sptr(s);
    const uint32_t sBh = sAh + PA_TILE*2;

    #pragma unroll
    for (int ks=0; ks<4; ks++){
      uint32_t ah[2][4], bh[2][4];
      #pragma unroll
      for (int mi=0; mi<2; mi++){
        uint32_t off = (uint32_t)((wm + mi*16 + arow)*PPADH + ks*16 + acol8)*2;
        ldsm4(ah[mi], sAh + off);
      }
      #pragma unroll
      for (int p=0; p<2; p++){
        uint32_t off = (uint32_t)((wn + p*16 + brow)*PPADH + ks*16 + bsel)*2;
        ldsm4(bh[p], sBh + off);
      }
      #pragma unroll
      for (int mi=0; mi<2; mi++)
        #pragma unroll
        for (int p=0; p<2; p++)
          #pragma unroll
          for (int h=0; h<2; h++)
            mma_h(acc[mi][p*2+h], ah[mi], &bh[p][h*2]);
    }
    __syncthreads();
  }

  const int colblk = wid>>1;
  #pragma unroll
  for (int mi=0; mi<2; mi++){
    #pragma unroll
    for (int qh=0; qh<2; qh++){
      float sv = 0.f;
      #pragma unroll
      for (int ni=0; ni<4; ni++)
        sv += fabsf(acc[mi][ni][qh*2]) + fabsf(acc[mi][ni][qh*2+1]);
      sv += __shfl_xor_sync(0xffffffffu, sv, 1);
      sv += __shfl_xor_sync(0xffffffffu, sv, 2);
      if ((lane&3)==0)
        ssum[colblk][wm + mi*16 + qh*8 + (lane>>2)] = sv;
    }
  }
  __syncthreads();
  if (tid < 64){
    float str = ssum[0][tid] + ssum[1][tid];
    float sct = ssum[2][tid] + ssum[3][tid];
    sscale[tid] = __fdividef(1.f, 1e-8f + str*sct);
  }
  __syncthreads();
  #pragma unroll
  for (int mi=0; mi<2; mi++){
    #pragma unroll
    for (int ni=0; ni<4; ni++){
      #pragma unroll
      for (int q=0; q<4; q++){
        int rloc = wm + mi*16 + (q>>1)*8 + (lane>>2);
        int t = bm + rloc;
        int col = wn + (lane&3)*2 + ni*8 + (q&1);
        float vabs = fabsf(acc[mi][ni][q]);
        if (col < 64) g_u[t*TR_ + col] = vabs;
        else          g_v[t*CC_ + col - 64] = vabs * sscale[rloc];
      }
    }
  }
}

// ---------------- scan ----------------
__device__ __forceinline__ void make_decay(float ai, float bj, float& dre, float& dim){
  double rho = exp(-(double)fabsf(ai));
  double sb, cb; sincos((double)bj, &sb, &cb);
  dre = (float)(rho*cb); dim = (float)(rho*sb);
}

__global__ void scan_passA(const unsigned* __restrict__ start,
                           const float* __restrict__ a, const float* __restrict__ b,
                           int layer){
  const int i = blockIdx.y;
  const int c = blockIdx.x;
  const int j = threadIdx.x;
  const float ai = a[layer*TR_ + i];
  const float bj = b[layer*CC_ + j];
  float dre, dim;
  make_decay(ai, bj, dre, dim);
  float sre=0.f, sim=0.f;
  int reset = 0;
  const int t0 = c*CHUNK_;
  for (int t=t0; t<t0+CHUNK_; t++){
    if (start[t]){ sre=0.f; sim=0.f; reset=1; }
    float p = g_u[t*TR_+i]*g_v[t*CC_+j];
    float nre = fmaf(sre,dre, fmaf(-sim,dim,p));
    float nim = fmaf(sre,dim, sim*dre);
    sre=nre; sim=nim;
  }
  const int ch = i*CC_+j;
  g_Bend[c*NCH_+ch]=make_float2(sre,sim);
  float2 A;
  if (reset){ A=make_float2(0.f,0.f); }
  else {
    double rhoL = exp(-(double)fabsf(ai)*(double)CHUNK_);
    double sL,cL; sincos((double)bj*(double)CHUNK_, &sL,&cL);
    A = make_float2((float)(rhoL*cL), (float)(rhoL*sL));
  }
  g_Amat[c*NCH_+ch]=A;
}

// pass C with folded chunk-combine
__global__ void scan_passC(const unsigned* __restrict__ start,
                           const float* __restrict__ a, const float* __restrict__ b,
                           const float* __restrict__ state, int layer){
  const int i = blockIdx.y, c = blockIdx.x, j = threadIdx.x;
  float dre, dim;
  make_decay(a[layer*TR_+i], b[layer*CC_+j], dre, dim);
  const int ch = i*CC_+j;
  float sre = state[layer*NCH_ + ch];
  float sim = 0.f;
  for (int cc=0; cc<c; cc++){
    float2 A = g_Amat[cc*NCH_+ch];
    float2 B = g_Bend[cc*NCH_+ch];
    float nr = A.x*sre - A.y*sim + B.x;
    float ni = A.x*sim + A.y*sre + B.y;
    sre=nr; sim=ni;
  }
  const int t0=c*CHUNK_;
  for (int t=t0;t<t0+CHUNK_;t++){
    if (start[t]){ sre=0.f; sim=0.f; }
    float p = g_u[t*TR_+i]*g_v[t*CC_+j];
    float nre = fmaf(sre,dre, fmaf(-sim,dim,p));
    float nim = fmaf(sre,dim, sim*dre);
    sre=nre; sim=nim;
    float r2 = fmaf(sre,sre, sim*sim);
    float f;
    if (r2 > 1e-24f){
      float rr = sqrtf(r2);
      f = __fdividef(log1pf(rr), rr);
    } else {
      f = 1.f;
    }
    size_t o0 = (size_t)t*F_ + ch;
    g_sclh[o0]        = __float2half_rn(f*sim);
    g_sclh[o0 + NCH_] = __float2half_rn(f*sre);
  }
}

// ================= LayerNorm + leaky ReLU (reads nparts split-K partials) =================
__device__ __forceinline__ void reduce2(float &s, float &ss){
  __shared__ float sh[8], sh2[8];
  int lane = threadIdx.x & 31, w = threadIdx.x >> 5;
  #pragma unroll
  for (int o=16;o>0;o>>=1){
    s  += __shfl_down_sync(0xffffffffu, s,  o);
    ss += __shfl_down_sync(0xffffffffu, ss, o);
  }
  if (lane==0){ sh[w]=s; sh2[w]=ss; }
  __syncthreads();
  if (w==0){
    s  = (lane<8)? sh[lane]  : 0.f;
    ss = (lane<8)? sh2[lane] : 0.f;
    #pragma unroll
    for (int o=4;o>0;o>>=1){
      s  += __shfl_down_sync(0xffffffffu, s,  o);
      ss += __shfl_down_sync(0xffffffffu, ss, o);
    }
    if (lane==0){ sh[0]=s; sh2[0]=ss; }
  }
  __syncthreads();
  s = sh[0]; ss = sh2[0];
}

__global__ void ln_leaky(const float* __restrict__ zin, int nparts,
                         const float* __restrict__ bias,
                         const float* __restrict__ gamma, const float* __restrict__ beta,
                         float* __restrict__ zout, float* __restrict__ xacc,
                         __half* __restrict__ zh, __half* __restrict__ xh){
  const int t = blockIdx.x;
  const int tid = threadIdx.x;
  float v0 = bias[tid];
  float v1 = bias[256+tid];
  for (int p=0; p<nparts; p++){
    v0 += zin[(size_t)p*T_*D_ + t*D_ + tid];
    v1 += zin[(size_t)p*T_*D_ + t*D_ + 256 + tid];
  }
  float s = v0+v1;
  float ss = v0*v0 + v1*v1;
  reduce2(s, ss);
  float m = s * (1.f/512.f);
  float var = ss * (1.f/512.f) - m*m;
  float rinv = rsqrtf(var + 1e-5f);
  float y0 = (v0 - m)*rinv*gamma[tid]     + beta[tid];
  float y1 = (v1 - m)*rinv*gamma[256+tid] + beta[256+tid];
  y0 = (y0 > 0.f) ? y0 : 0.01f*y0;
  y1 = (y1 > 0.f) ? y1 : 0.01f*y1;
  if (zout){
    zout[t*D_ + tid]       = y0;
    zout[t*D_ + 256 + tid] = y1;
  }
  if (xacc){
    float x0 = xacc[t*D_ + tid]       + y0;
    float x1 = xacc[t*D_ + 256 + tid] + y1;
    xacc[t*D_ + tid]       = x0;
    xacc[t*D_ + 256 + tid] = x1;
    if (xh){
      xh[t*D_ + tid]       = __float2half_rn(x0);
      xh[t*D_ + 256 + tid] = __float2half_rn(x1);
    }
  }
  if (zh){
    zh[t*D_ + tid]       = __float2half_rn(y0);
    zh[t*D_ + 256 + tid] = __float2half_rn(y1);
  }
}

// ================= launcher =================
extern "C" void kernel_launch(void* const* d_in, const int* in_sizes, int n_in,
                              void* d_out, int out_size) {
  const float*    x     = (const float*)d_in[0];
  const float*    state = (const float*)d_in[1];
  const unsigned* start = (const unsigned*)d_in[2];
  const float*    Wtr   = (const float*)d_in[3];
  const float*    Wc    = (const float*)d_in[4];
  const float*    a     = (const float*)d_in[5];
  const float*    b     = (const float*)d_in[6];
  const float*    W0    = (const float*)d_in[7];
  const float*    b0    = (const float*)d_in[8];
  const float*    g0    = (const float*)d_in[9];
  const float*    beta0 = (const float*)d_in[10];
  const float*    W1    = (const float*)d_in[11];
  const float*    b1    = (const float*)d_in[12];
  const float*    g1    = (const float*)d_in[13];
  const float*    beta1 = (const float*)d_in[14];
  float* out = (float*)d_out;

  float *px, *php, *pzt;
  __half *psh, *pw0h, *pw1h, *pwph, *pz0h, *pxh;
  cudaGetSymbolAddress((void**)&px,    g_x);
  cudaGetSymbolAddress((void**)&php,   g_hp);
  cudaGetSymbolAddress((void**)&pzt,   g_ztmp);
  cudaGetSymbolAddress((void**)&psh,   g_sclh);
  cudaGetSymbolAddress((void**)&pw0h,  g_w0h);
  cudaGetSymbolAddress((void**)&pw1h,  g_w1h);
  cudaGetSymbolAddress((void**)&pwph,  g_wph);
  cudaGetSymbolAddress((void**)&pz0h,  g_z0h);
  cudaGetSymbolAddress((void**)&pxh,   g_xh);

  cudaFuncSetAttribute(gemm1,   cudaFuncAttributeMaxDynamicSharedMemorySize, GEMM1_SMEM);
  cudaFuncSetAttribute(proj_uv, cudaFuncAttributeMaxDynamicSharedMemorySize, PROJ_SMEM);

  prep_all<<<(NPREP + 255)/256, 256>>>(W0, W1, Wtr, Wc, x);

  for (int l=0; l<L_; l++){
    // fused projection + uv
    proj_uv<<<dim3(1, T_/64), 256, PROJ_SMEM>>>(pxh, pwph + (size_t)l*128*D_);

    scan_passA<<<dim3(NCHUNK_, TR_), CC_>>>(start, a, b, l);
    scan_passC<<<dim3(NCHUNK_, TR_), CC_>>>(start, a, b, state, l);

    // h = scaled @ W0^T  (M=4096, N=512, K=8192), split-K=4 -> 512 CTAs
    gemm1<<<dim3(D_/128, T_/128, NSPLIT_), 256, GEMM1_SMEM>>>(
        psh, pw0h + (size_t)l*D_*F_, php, F_, F_/NSPLIT_, D_);
    ln_leaky<<<T_, 256>>>(php, NSPLIT_, b0 + l*D_, g0 + l*D_, beta0 + l*D_,
                          nullptr, nullptr, pz0h, nullptr);

    // h = z0 @ W1^T  (M=4096, N=512, K=512), no split
    gemm1<<<dim3(D_/128, T_/128, 1), 256, GEMM1_SMEM>>>(
        pz0h, pw1h + (size_t)l*D_*D_, php, D_, D_, D_);
    float* zo = (l == L_-1) ? out : pzt;
    bool last = (l == L_-1);
    ln_leaky<<<T_, 256>>>(php, 1, b1 + l*D_, g1 + l*D_, beta1 + l*D_,
                          zo, px, nullptr, last ? nullptr : pxh);
  }
}

// round 11
// speedup vs baseline: 2.8129x; 1.1916x over previous
#include <cuda_runtime.h>
#include <cuda_fp16.h>
#include <math.h>
#include <stdint.h>

#define T_ 4096
#define D_ 512
#define TR_ 64
#define CC_ 64
#define L_ 3
#define F_ 8192
#define NCH_ 4096
#define NCHUNK_ 64
#define CHUNK_ 64
#define NSPLIT_ 4

// ---------------- scratch ----------------
__device__ float g_x[T_*D_];
__device__ float g_u[T_*TR_];
__device__ float g_v[T_*CC_];
__device__ float2 g_Bend[NCHUNK_*NCH_];
__device__ float2 g_Amat[NCHUNK_*NCH_];
__device__ float2 g_dec[L_*NCH_];    // per-step decay e^{-|a|} e^{ib}
__device__ float2 g_decL[L_*NCH_];   // per-chunk decay (CHUNK_ steps)
__device__ float g_hp[NSPLIT_][T_*D_];
__device__ float g_ztmp[T_*D_];
__device__ __half g_sclh[(size_t)T_*F_];
__device__ __half g_w0h[L_*D_*F_];
__device__ __half g_w1h[L_*D_*D_];
__device__ __half g_wph[L_*128*D_];
__device__ __half g_z0h[T_*D_];
__device__ __half g_xh[T_*D_];

// ---------------- low-level helpers (baseline PTX @ compute_103) ----------------
__device__ __forceinline__ uint32_t sptr(const void* p){
  return (uint32_t)__cvta_generic_to_shared(p);
}
__device__ __forceinline__ void cp16(uint32_t s, const void* g){
  asm volatile("cp.async.cg.shared.global [%0], [%1], 16;" :: "r"(s), "l"(g));
}
#define CP_COMMIT() asm volatile("cp.async.commit_group;" ::: "memory")
#define CP_WAIT(n)  asm volatile("cp.async.wait_group %0;" :: "n"(n) : "memory")

__device__ __forceinline__ void ldsm4(uint32_t* r, uint32_t a){
  asm volatile("ldmatrix.sync.aligned.m8n8.x4.shared.b16 {%0,%1,%2,%3}, [%4];"
    : "=r"(r[0]),"=r"(r[1]),"=r"(r[2]),"=r"(r[3]) : "r"(a));
}
__device__ __forceinline__ void mma_h(float* d, const uint32_t* a, const uint32_t* b){
  asm volatile("mma.sync.aligned.m16n8k16.row.col.f32.f16.f16.f32 "
    "{%0,%1,%2,%3}, {%4,%5,%6,%7}, {%8,%9}, {%0,%1,%2,%3};"
    : "+f"(d[0]),"+f"(d[1]),"+f"(d[2]),"+f"(d[3])
    : "r"(a[0]),"r"(a[1]),"r"(a[2]),"r"(a[3]), "r"(b[0]),"r"(b[1]));
}

// ---------------- merged prep kernel ----------------
#define NW0 (L_*D_*F_)
#define NW1 (L_*D_*D_)
#define NWP (L_*128*D_)
#define NX  (T_*D_)
#define NDEC (L_*NCH_)
#define NPREP (NW0+NW1+NWP+NX+NDEC)

__global__ void prep_all(const float* __restrict__ W0, const float* __restrict__ W1,
                         const float* __restrict__ Wtr, const float* __restrict__ Wc,
                         const float* __restrict__ x,
                         const float* __restrict__ a, const float* __restrict__ b){
  int i = blockIdx.x*blockDim.x + threadIdx.x;
  if (i < NW0){
    g_w0h[i] = __float2half_rn(W0[i]);
  } else if (i < NW0+NW1){
    int k = i - NW0;
    g_w1h[k] = __float2half_rn(W1[k]);
  } else if (i < NW0+NW1+NWP){
    int idx = i - NW0 - NW1;
    int l = idx / (128*D_);
    int rem = idx % (128*D_);
    int row = rem / D_, k = rem % D_;
    float v = (row < 64) ? Wtr[((size_t)l*64+row)*D_+k] : Wc[((size_t)l*64+row-64)*D_+k];
    g_wph[idx] = __float2half_rn(v);
  } else if (i < NW0+NW1+NWP+NX){
    int k = i - NW0 - NW1 - NWP;
    float v = x[k];
    g_x[k] = v;
    g_xh[k] = __float2half_rn(v);
  } else if (i < NPREP){
    int k = i - NW0 - NW1 - NWP - NX;
    int l = k / NCH_;
    int ch = k % NCH_;
    int i0 = ch / CC_, j0 = ch % CC_;
    double ai = fabs((double)a[l*TR_+i0]);
    double bj = (double)b[l*CC_+j0];
    double rho = exp(-ai);
    double sb, cb; sincos(bj, &sb, &cb);
    g_dec[k] = make_float2((float)(rho*cb), (float)(rho*sb));
    double rhoL = exp(-ai*(double)CHUNK_);
    double sL, cL; sincos(bj*(double)CHUNK_, &sL, &cL);
    g_decL[k] = make_float2((float)(rhoL*cL), (float)(rhoL*sL));
  }
}

// ================= 1-term fp16 GEMM with split-K =================
#define PADH 72
#define TILEH (128*PADH)
#define STAGE1 (2*TILEH)
#define GEMM1_SMEM (3*STAGE1*2)        // 110592 B

__device__ __forceinline__ void stage_load1(
    __half* s, const __half* Ah, const __half* Bh,
    int bm, int bn, int K, int k0, int tid)
{
  const __half* src[2] = {Ah, Bh};
  #pragma unroll
  for (int t=0;t<2;t++){
    int rb = (t==0)? bm : bn;
    #pragma unroll
    for (int q=0;q<4;q++){
      int chunk = tid + q*256;
      int row = chunk>>3, cc = chunk&7;
      uint32_t so = sptr(s + t*TILEH + row*PADH + cc*8);
      cp16(so, src[t] + (size_t)(rb+row)*K + k0 + cc*8);
    }
  }
}

__global__ void __launch_bounds__(256, 2)
gemm1(const __half* __restrict__ Ah, const __half* __restrict__ Bh,
      float* __restrict__ Cbase, int K, int KS, int Nc)
{
  extern __shared__ __half smh[];
  const int tid = threadIdx.x;
  const int wid = tid>>5, lane = tid&31;
  const int bm = blockIdx.y*128, bn = blockIdx.x*128;
  const int kz = blockIdx.z;
  const int kbase = kz * KS;
  float* C = Cbase + (size_t)kz * T_ * D_;
  const int wm = (wid>>1)*32;
  const int wn = (wid&1)*64;
  const int KT = KS>>6;

  float acc[2][8][4];
  #pragma unroll
  for (int i=0;i<2;i++)
    #pragma unroll
    for (int j=0;j<8;j++)
      #pragma unroll
      for (int q=0;q<4;q++) acc[i][j][q]=0.f;

  stage_load1(smh, Ah, Bh, bm, bn, K, kbase, tid);
  CP_COMMIT();
  if (KT > 1){
    stage_load1(smh + STAGE1, Ah, Bh, bm, bn, K, kbase + 64, tid);
    CP_COMMIT();
  }

  const int arow = lane & 15;
  const int acol8 = (lane>>4)*8;
  const int brow = (lane&7) + ((lane>>4)<<3);
  const int bsel = ((lane>>3)&1)*8;

  int bufc = 0;
  for (int c=0; c<KT; c++){
    if (c+1 < KT) { CP_WAIT(1); } else { CP_WAIT(0); }
    __syncthreads();

    __half* s = smh + bufc*STAGE1;
    const uint32_t sAh = sptr(s);
    const uint32_t sBh = sAh + TILEH*2;

    #pragma unroll
    for (int ks=0; ks<4; ks++){
      uint32_t ah[2][4], bh[4][4];
      #pragma unroll
      for (int mi=0; mi<2; mi++){
        uint32_t off = (uint32_t)((wm + mi*16 + arow)*PADH + ks*16 + acol8)*2;
        ldsm4(ah[mi], sAh + off);
      }
      #pragma unroll
      for (int p=0; p<4; p++){
        uint32_t off = (uint32_t)((wn + p*16 + brow)*PADH + ks*16 + bsel)*2;
        ldsm4(bh[p], sBh + off);
      }
      #pragma unroll
      for (int mi=0; mi<2; mi++)
        #pragma unroll
        for (int p=0; p<4; p++)
          #pragma unroll
          for (int h=0; h<2; h++)
            mma_h(acc[mi][p*2+h], ah[mi], &bh[p][h*2]);
    }

    if (c+2 < KT){
      int buf2 = bufc + 2; if (buf2 >= 3) buf2 -= 3;
      stage_load1(smh + buf2*STAGE1, Ah, Bh, bm, bn, K, kbase + (c+2)*64, tid);
      CP_COMMIT();
    }
    bufc++; if (bufc == 3) bufc = 0;
  }

  #pragma unroll
  for (int mi=0; mi<2; mi++){
    const int r0 = bm + wm + mi*16 + (lane>>2);
    const int c0 = bn + wn + (lane&3)*2;
    #pragma unroll
    for (int ni=0; ni<8; ni++){
      *(float2*)(C + (size_t)r0*Nc + c0 + ni*8)     = make_float2(acc[mi][ni][0], acc[mi][ni][1]);
      *(float2*)(C + (size_t)(r0+8)*Nc + c0 + ni*8) = make_float2(acc[mi][ni][2], acc[mi][ni][3]);
    }
  }
}

// ================= fused projection + uv (1-term) =================
#define PPADH 72
#define PA_TILE (64*PPADH)
#define PB_TILE (128*PPADH)
#define PSTAGE (PA_TILE + PB_TILE)
#define PROJ_SMEM (2*PSTAGE*2)

__device__ __forceinline__ void stage_load_proj(
    __half* s, const __half* Ah, const __half* Bh,
    int bm, int K, int k0, int tid)
{
  #pragma unroll
  for (int q=0;q<2;q++){
    int chunk = tid + q*256;
    int row = chunk>>3, cc = chunk&7;
    uint32_t so = sptr(s + row*PPADH + cc*8);
    cp16(so, Ah + (size_t)(bm+row)*K + k0 + cc*8);
  }
  #pragma unroll
  for (int q=0;q<4;q++){
    int chunk = tid + q*256;
    int row = chunk>>3, cc = chunk&7;
    uint32_t so = sptr(s + PA_TILE + row*PPADH + cc*8);
    cp16(so, Bh + (size_t)row*K + k0 + cc*8);
  }
}

__global__ void __launch_bounds__(256)
proj_uv(const __half* __restrict__ Ah, const __half* __restrict__ Bh)
{
  extern __shared__ __half smh[];
  __shared__ float ssum[4][64];
  __shared__ float sscale[64];
  const int tid = threadIdx.x;
  const int wid = tid>>5, lane = tid&31;
  const int bm = blockIdx.y*64;
  const int wm = (wid&1)*32;
  const int wn = (wid>>1)*32;
  const int K = D_;
  const int KT = K>>6;

  float acc[2][4][4];
  #pragma unroll
  for (int i=0;i<2;i++)
    #pragma unroll
    for (int j=0;j<4;j++)
      #pragma unroll
      for (int q=0;q<4;q++) acc[i][j][q]=0.f;

  stage_load_proj(smh, Ah, Bh, bm, K, 0, tid);
  CP_COMMIT();

  const int arow = lane & 15;
  const int acol8 = (lane>>4)*8;
  const int brow = (lane&7) + ((lane>>4)<<3);
  const int bsel = ((lane>>3)&1)*8;

  for (int c=0; c<KT; c++){
    if (c+1 < KT){
      stage_load_proj(smh + ((c+1)&1)*PSTAGE, Ah, Bh, bm, K, (c+1)*64, tid);
      CP_COMMIT();
      CP_WAIT(1);
    } else {
      CP_WAIT(0);
    }
    __syncthreads();

    __half* s = smh + (c&1)*PSTAGE;
    const uint32_t sAh = sptr(s);
    const uint32_t sBh = sAh + PA_TILE*2;

    #pragma unroll
    for (int ks=0; ks<4; ks++){
      uint32_t ah[2][4], bh[2][4];
      #pragma unroll
      for (int mi=0; mi<2; mi++){
        uint32_t off = (uint32_t)((wm + mi*16 + arow)*PPADH + ks*16 + acol8)*2;
        ldsm4(ah[mi], sAh + off);
      }
      #pragma unroll
      for (int p=0; p<2; p++){
        uint32_t off = (uint32_t)((wn + p*16 + brow)*PPADH + ks*16 + bsel)*2;
        ldsm4(bh[p], sBh + off);
      }
      #pragma unroll
      for (int mi=0; mi<2; mi++)
        #pragma unroll
        for (int p=0; p<2; p++)
          #pragma unroll
          for (int h=0; h<2; h++)
            mma_h(acc[mi][p*2+h], ah[mi], &bh[p][h*2]);
    }
    __syncthreads();
  }

  const int colblk = wid>>1;
  #pragma unroll
  for (int mi=0; mi<2; mi++){
    #pragma unroll
    for (int qh=0; qh<2; qh++){
      float sv = 0.f;
      #pragma unroll
      for (int ni=0; ni<4; ni++)
        sv += fabsf(acc[mi][ni][qh*2]) + fabsf(acc[mi][ni][qh*2+1]);
      sv += __shfl_xor_sync(0xffffffffu, sv, 1);
      sv += __shfl_xor_sync(0xffffffffu, sv, 2);
      if ((lane&3)==0)
        ssum[colblk][wm + mi*16 + qh*8 + (lane>>2)] = sv;
    }
  }
  __syncthreads();
  if (tid < 64){
    float str = ssum[0][tid] + ssum[1][tid];
    float sct = ssum[2][tid] + ssum[3][tid];
    sscale[tid] = __fdividef(1.f, 1e-8f + str*sct);
  }
  __syncthreads();
  #pragma unroll
  for (int mi=0; mi<2; mi++){
    #pragma unroll
    for (int ni=0; ni<4; ni++){
      #pragma unroll
      for (int q=0; q<4; q++){
        int rloc = wm + mi*16 + (q>>1)*8 + (lane>>2);
        int t = bm + rloc;
        int col = wn + (lane&3)*2 + ni*8 + (q&1);
        float vabs = fabsf(acc[mi][ni][q]);
        if (col < 64) g_u[t*TR_ + col] = vabs;
        else          g_v[t*CC_ + col - 64] = vabs * sscale[rloc];
      }
    }
  }
}

// ---------------- scan (decay from precomputed tables) ----------------
__global__ void scan_passA(const unsigned* __restrict__ start, int layer){
  const int i = blockIdx.y;
  const int c = blockIdx.x;
  const int j = threadIdx.x;
  const int ch = i*CC_+j;
  float2 d = g_dec[layer*NCH_ + ch];
  const float dre = d.x, dim = d.y;
  float sre=0.f, sim=0.f;
  int reset = 0;
  const int t0 = c*CHUNK_;
  #pragma unroll 4
  for (int t=t0; t<t0+CHUNK_; t++){
    if (start[t]){ sre=0.f; sim=0.f; reset=1; }
    float p = g_u[t*TR_+i]*g_v[t*CC_+j];
    float nre = fmaf(sre,dre, fmaf(-sim,dim,p));
    float nim = fmaf(sre,dim, sim*dre);
    sre=nre; sim=nim;
  }
  g_Bend[c*NCH_+ch]=make_float2(sre,sim);
  float2 A = make_float2(0.f, 0.f);
  if (!reset) A = g_decL[layer*NCH_ + ch];
  g_Amat[c*NCH_+ch]=A;
}

// pass C with folded chunk-combine
__global__ void scan_passC(const unsigned* __restrict__ start,
                           const float* __restrict__ state, int layer){
  const int i = blockIdx.y, c = blockIdx.x, j = threadIdx.x;
  const int ch = i*CC_+j;
  float2 d = g_dec[layer*NCH_ + ch];
  const float dre = d.x, dim = d.y;
  float sre = state[layer*NCH_ + ch];
  float sim = 0.f;
  for (int cc=0; cc<c; cc++){
    float2 A = g_Amat[cc*NCH_+ch];
    float2 B = g_Bend[cc*NCH_+ch];
    float nr = A.x*sre - A.y*sim + B.x;
    float ni = A.x*sim + A.y*sre + B.y;
    sre=nr; sim=ni;
  }
  const int t0=c*CHUNK_;
  #pragma unroll 4
  for (int t=t0;t<t0+CHUNK_;t++){
    if (start[t]){ sre=0.f; sim=0.f; }
    float p = g_u[t*TR_+i]*g_v[t*CC_+j];
    float nre = fmaf(sre,dre, fmaf(-sim,dim,p));
    float nim = fmaf(sre,dim, sim*dre);
    sre=nre; sim=nim;
    float r2 = fmaf(sre,sre, sim*sim);
    float f;
    if (r2 > 1e-24f){
      float rr = sqrtf(r2);
      f = __fdividef(log1pf(rr), rr);
    } else {
      f = 1.f;
    }
    size_t o0 = (size_t)t*F_ + ch;
    g_sclh[o0]        = __float2half_rn(f*sim);
    g_sclh[o0 + NCH_] = __float2half_rn(f*sre);
  }
}

// ================= LayerNorm + leaky ReLU =================
__device__ __forceinline__ void reduce2(float &s, float &ss){
  __shared__ float sh[8], sh2[8];
  int lane = threadIdx.x & 31, w = threadIdx.x >> 5;
  #pragma unroll
  for (int o=16;o>0;o>>=1){
    s  += __shfl_down_sync(0xffffffffu, s,  o);
    ss += __shfl_down_sync(0xffffffffu, ss, o);
  }
  if (lane==0){ sh[w]=s; sh2[w]=ss; }
  __syncthreads();
  if (w==0){
    s  = (lane<8)? sh[lane]  : 0.f;
    ss = (lane<8)? sh2[lane] : 0.f;
    #pragma unroll
    for (int o=4;o>0;o>>=1){
      s  += __shfl_down_sync(0xffffffffu, s,  o);
      ss += __shfl_down_sync(0xffffffffu, ss, o);
    }
    if (lane==0){ sh[0]=s; sh2[0]=ss; }
  }
  __syncthreads();
  s = sh[0]; ss = sh2[0];
}

__global__ void ln_leaky(const float* __restrict__ zin, int nparts,
                         const float* __restrict__ bias,
                         const float* __restrict__ gamma, const float* __restrict__ beta,
                         float* __restrict__ zout, float* __restrict__ xacc,
                         __half* __restrict__ zh, __half* __restrict__ xh){
  const int t = blockIdx.x;
  const int tid = threadIdx.x;
  float v0 = bias[tid];
  float v1 = bias[256+tid];
  for (int p=0; p<nparts; p++){
    v0 += zin[(size_t)p*T_*D_ + t*D_ + tid];
    v1 += zin[(size_t)p*T_*D_ + t*D_ + 256 + tid];
  }
  float s = v0+v1;
  float ss = v0*v0 + v1*v1;
  reduce2(s, ss);
  float m = s * (1.f/512.f);
  float var = ss * (1.f/512.f) - m*m;
  float rinv = rsqrtf(var + 1e-5f);
  float y0 = (v0 - m)*rinv*gamma[tid]     + beta[tid];
  float y1 = (v1 - m)*rinv*gamma[256+tid] + beta[256+tid];
  y0 = (y0 > 0.f) ? y0 : 0.01f*y0;
  y1 = (y1 > 0.f) ? y1 : 0.01f*y1;
  if (zout){
    zout[t*D_ + tid]       = y0;
    zout[t*D_ + 256 + tid] = y1;
  }
  if (xacc){
    float x0 = xacc[t*D_ + tid]       + y0;
    float x1 = xacc[t*D_ + 256 + tid] + y1;
    xacc[t*D_ + tid]       = x0;
    xacc[t*D_ + 256 + tid] = x1;
    if (xh){
      xh[t*D_ + tid]       = __float2half_rn(x0);
      xh[t*D_ + 256 + tid] = __float2half_rn(x1);
    }
  }
  if (zh){
    zh[t*D_ + tid]       = __float2half_rn(y0);
    zh[t*D_ + 256 + tid] = __float2half_rn(y1);
  }
}

// ================= launcher =================
extern "C" void kernel_launch(void* const* d_in, const int* in_sizes, int n_in,
                              void* d_out, int out_size) {
  const float*    x     = (const float*)d_in[0];
  const float*    state = (const float*)d_in[1];
  const unsigned* start = (const unsigned*)d_in[2];
  const float*    Wtr   = (const float*)d_in[3];
  const float*    Wc    = (const float*)d_in[4];
  const float*    a     = (const float*)d_in[5];
  const float*    b     = (const float*)d_in[6];
  const float*    W0    = (const float*)d_in[7];
  const float*    b0    = (const float*)d_in[8];
  const float*    g0    = (const float*)d_in[9];
  const float*    beta0 = (const float*)d_in[10];
  const float*    W1    = (const float*)d_in[11];
  const float*    b1    = (const float*)d_in[12];
  const float*    g1    = (const float*)d_in[13];
  const float*    beta1 = (const float*)d_in[14];
  float* out = (float*)d_out;

  float *px, *php, *pzt;
  __half *psh, *pw0h, *pw1h, *pwph, *pz0h, *pxh;
  cudaGetSymbolAddress((void**)&px,    g_x);
  cudaGetSymbolAddress((void**)&php,   g_hp);
  cudaGetSymbolAddress((void**)&pzt,   g_ztmp);
  cudaGetSymbolAddress((void**)&psh,   g_sclh);
  cudaGetSymbolAddress((void**)&pw0h,  g_w0h);
  cudaGetSymbolAddress((void**)&pw1h,  g_w1h);
  cudaGetSymbolAddress((void**)&pwph,  g_wph);
  cudaGetSymbolAddress((void**)&pz0h,  g_z0h);
  cudaGetSymbolAddress((void**)&pxh,   g_xh);

  cudaFuncSetAttribute(gemm1,   cudaFuncAttributeMaxDynamicSharedMemorySize, GEMM1_SMEM);
  cudaFuncSetAttribute(proj_uv, cudaFuncAttributeMaxDynamicSharedMemorySize, PROJ_SMEM);

  prep_all<<<(NPREP + 255)/256, 256>>>(W0, W1, Wtr, Wc, x, a, b);

  for (int l=0; l<L_; l++){
    proj_uv<<<dim3(1, T_/64), 256, PROJ_SMEM>>>(pxh, pwph + (size_t)l*128*D_);

    scan_passA<<<dim3(NCHUNK_, TR_), CC_>>>(start, l);
    scan_passC<<<dim3(NCHUNK_, TR_), CC_>>>(start, state, l);

    // h = scaled @ W0^T  (M=4096, N=512, K=8192), split-K=4
    gemm1<<<dim3(D_/128, T_/128, NSPLIT_), 256, GEMM1_SMEM>>>(
        psh, pw0h + (size_t)l*D_*F_, php, F_, F_/NSPLIT_, D_);
    ln_leaky<<<T_, 256>>>(php, NSPLIT_, b0 + l*D_, g0 + l*D_, beta0 + l*D_,
                          nullptr, nullptr, pz0h, nullptr);

    // h = z0 @ W1^T  (M=4096, N=512, K=512)
    gemm1<<<dim3(D_/128, T_/128, 1), 256, GEMM1_SMEM>>>(
        pz0h, pw1h + (size_t)l*D_*D_, php, D_, D_, D_);
    float* zo = (l == L_-1) ? out : pzt;
    bool last = (l == L_-1);
    ln_leaky<<<T_, 256>>>(php, 1, b1 + l*D_, g1 + l*D_, beta1 + l*D_,
                          zo, px, nullptr, last ? nullptr : pxh);
  }
}